// round 6
// baseline (speedup 1.0000x reference)
#include <cuda_runtime.h>
#include <cuda_bf16.h>
#include <math_constants.h>

// Problem constants (fixed by the dataset)
#define NN 50000
#define NE 800000
#define ETOT (NE + NN)       // edges + self loops = 850000
#define NG 64
#define HEADS 4
#define NSUB 8               // GraphNorm sub-partitions per graph

// ---------------- scratch (no cudaMalloc allowed) ----------------
__device__ float g_xl[NN * 128];
__device__ float g_xr[NN * 128];
__device__ float g_h1[NN * 128];
__device__ float g_h2[NN * 64];
__device__ float g_h3[NN * 8];
__device__ int   g_deg[NN];
__device__ int   g_off[NN + 1];
__device__ int   g_cursor[NN];
__device__ int   g_srcs[ETOT];
__device__ int   g_go[NG + 1];
__device__ float g_part[NG * NSUB * 2 * 128];
__device__ float g_mus[NG * 128];
__device__ float g_wr[NG * 128];

// ---------------- cp.async helpers ----------------
__device__ __forceinline__ void cp_async16(void* smem_ptr, const void* gmem_ptr, bool pred) {
    unsigned saddr = (unsigned)__cvta_generic_to_shared(smem_ptr);
    int sz = pred ? 16 : 0;
    asm volatile("cp.async.ca.shared.global [%0], [%1], 16, %2;\n"
                 :: "r"(saddr), "l"(gmem_ptr), "r"(sz));
}
__device__ __forceinline__ void cp_commit() { asm volatile("cp.async.commit_group;\n"); }
template <int N>
__device__ __forceinline__ void cp_wait() { asm volatile("cp.async.wait_group %0;\n" :: "n"(N)); }

// ---------------- CSR build ----------------
__global__ void zero_deg_kernel() {
    int i = blockIdx.x * blockDim.x + threadIdx.x;
    if (i < NN) g_deg[i] = 0;
}

__global__ void count_deg_kernel(const int* __restrict__ ei) {
    int e = blockIdx.x * blockDim.x + threadIdx.x;
    if (e >= ETOT) return;
    int dst = (e < NE) ? ei[NE + e] : (e - NE);
    atomicAdd(&g_deg[dst], 1);
}

// single-block exclusive scan (warp-shuffle based) + graph offsets
__global__ void scan_kernel(const int* __restrict__ batch) {
    __shared__ int wsum[32];
    __shared__ int carry_s;
    int t = threadIdx.x, lane = t & 31, wid = t >> 5;
    if (t == 0) carry_s = 0;
    __syncthreads();
    for (int base = 0; base < NN; base += 1024) {
        int i = base + t;
        int v = (i < NN) ? g_deg[i] : 0;
        int s = v;
#pragma unroll
        for (int o = 1; o < 32; o <<= 1) {
            int n = __shfl_up_sync(0xffffffffu, s, o);
            if (lane >= o) s += n;
        }
        if (lane == 31) wsum[wid] = s;
        __syncthreads();
        if (wid == 0) {
            int ws = wsum[lane];
#pragma unroll
            for (int o = 1; o < 32; o <<= 1) {
                int n = __shfl_up_sync(0xffffffffu, ws, o);
                if (lane >= o) ws += n;
            }
            wsum[lane] = ws;
        }
        __syncthreads();
        int carry = carry_s;
        int excl = carry + (wid ? wsum[wid - 1] : 0) + s - v;
        if (i < NN) { g_off[i] = excl; g_cursor[i] = excl; }
        int total = wsum[31];
        __syncthreads();
        if (t == 0) carry_s = carry + total;
        __syncthreads();
    }
    if (t == 0) g_off[NN] = carry_s;
    // fused graph offsets (batch is sorted)
    if (t <= NG) {
        if (t == NG) g_go[NG] = NN;
        else {
            int lo = 0, hi = NN;
            while (lo < hi) {
                int mid = (lo + hi) >> 1;
                if (batch[mid] < t) lo = mid + 1; else hi = mid;
            }
            g_go[t] = lo;
        }
    }
}

__global__ void scatter_kernel(const int* __restrict__ ei) {
    int e = blockIdx.x * blockDim.x + threadIdx.x;
    if (e >= ETOT) return;
    int src, dst;
    if (e < NE) { src = ei[e]; dst = ei[NE + e]; }
    else        { src = dst = e - NE; }
    int pos = atomicAdd(&g_cursor[dst], 1);
    g_srcs[pos] = src;
}

// ---------------- 3xTF32 tensor-core GEMM v3 ----------------
// Computes C0[N,M]=A@B0 and C1[N,M]=A@B1 over the concatenated column space
// [B0|B1] (total 2M cols). Block tile 128x128, warp grid 2x4, warp tile 64x32.
__device__ __forceinline__ unsigned f2tf32(float f) {
    unsigned r;
    asm("cvt.rna.tf32.f32 %0, %1;" : "=r"(r) : "f"(f));
    return r;
}
__device__ __forceinline__ void split_tf32(float v, unsigned& hi, unsigned& lo) {
    hi = f2tf32(v);
    lo = f2tf32(v - __uint_as_float(hi));
}
__device__ __forceinline__ void mma_tf32(float c[4], unsigned a0, unsigned a1,
                                         unsigned a2, unsigned a3,
                                         unsigned b0, unsigned b1) {
    asm volatile(
        "mma.sync.aligned.m16n8k8.row.col.f32.tf32.tf32.f32 "
        "{%0,%1,%2,%3}, {%4,%5,%6,%7}, {%8,%9}, {%0,%1,%2,%3};\n"
        : "+f"(c[0]), "+f"(c[1]), "+f"(c[2]), "+f"(c[3])
        : "r"(a0), "r"(a1), "r"(a2), "r"(a3), "r"(b0), "r"(b1));
}

__global__ __launch_bounds__(256, 1) void gemm_tf32_dual(
    const float* __restrict__ A,
    const float* __restrict__ Bp0, const float* __restrict__ Bp1,
    float* __restrict__ Cp0, float* __restrict__ Cp1,
    int N, int K, int M) {
    __shared__ float As[2][128][20];   // stride 20: conflict-free a-frag LDS
    __shared__ float Bs[2][16][136];   // stride 136: conflict-free b-frag LDS

    int t = threadIdx.x;
    int w = t >> 5, lane = t & 31;
    int wr = w >> 2, wc = w & 3;       // 2x4 warp grid
    int grp = lane >> 2, tg = lane & 3;
    int row0 = blockIdx.y * 128;
    int col0 = blockIdx.x * 128;       // over concatenated 2M cols
    int T2 = 2 * M;

    float c[4][4][4];
#pragma unroll
    for (int i = 0; i < 4; i++)
#pragma unroll
        for (int j = 0; j < 4; j++)
#pragma unroll
            for (int k = 0; k < 4; k++) c[i][j][k] = 0.f;

    auto load_tiles = [&](int stage, int k0) {
        // A tile 128x16 = 512 float4, 2 per thread
#pragma unroll
        for (int i = t; i < 512; i += 256) {
            int r = i >> 2, c4 = (i & 3) * 4;
            bool p = (row0 + r) < N;
            const float* src = p ? (A + (size_t)(row0 + r) * K + k0 + c4) : A;
            cp_async16(&As[stage][r][c4], src, p);
        }
        // B tile 16x128 = 512 float4, 2 per thread (cols from [B0|B1])
#pragma unroll
        for (int i = t; i < 512; i += 256) {
            int r = i >> 5, c4 = (i & 31) * 4;
            int gcol = col0 + c4;
            bool p = gcol < T2;
            const float* Bsel = (gcol >= M) ? Bp1 : Bp0;
            int gc = (gcol >= M) ? gcol - M : gcol;
            const float* src = p ? (Bsel + (size_t)(k0 + r) * M + gc) : Bp0;
            cp_async16(&Bs[stage][r][c4], src, p);
        }
    };

    int KT = K >> 4;
    load_tiles(0, 0);
    cp_commit();

    for (int kt = 0; kt < KT; kt++) {
        int cur = kt & 1;
        if (kt + 1 < KT) {
            load_tiles(cur ^ 1, (kt + 1) << 4);
            cp_commit();
            cp_wait<1>();
        } else {
            cp_wait<0>();
        }
        __syncthreads();

#pragma unroll
        for (int kk = 0; kk < 16; kk += 8) {
            unsigned ah[4][4], al[4][4];
#pragma unroll
            for (int mt = 0; mt < 4; mt++) {
                int r0 = wr * 64 + mt * 16;
                float a0 = As[cur][r0 + grp][kk + tg];
                float a1 = As[cur][r0 + grp + 8][kk + tg];
                float a2 = As[cur][r0 + grp][kk + tg + 4];
                float a3 = As[cur][r0 + grp + 8][kk + tg + 4];
                split_tf32(a0, ah[mt][0], al[mt][0]);
                split_tf32(a1, ah[mt][1], al[mt][1]);
                split_tf32(a2, ah[mt][2], al[mt][2]);
                split_tf32(a3, ah[mt][3], al[mt][3]);
            }
#pragma unroll
            for (int nt = 0; nt < 4; nt++) {
                int ci = wc * 32 + nt * 8 + grp;
                float b0 = Bs[cur][kk + tg][ci];
                float b1 = Bs[cur][kk + tg + 4][ci];
                unsigned bh0, bl0, bh1, bl1;
                split_tf32(b0, bh0, bl0);
                split_tf32(b1, bh1, bl1);
#pragma unroll
                for (int mt = 0; mt < 4; mt++) {
                    mma_tf32(c[mt][nt], ah[mt][0], ah[mt][1], ah[mt][2], ah[mt][3], bh0, bh1);
                    mma_tf32(c[mt][nt], al[mt][0], al[mt][1], al[mt][2], al[mt][3], bh0, bh1);
                    mma_tf32(c[mt][nt], ah[mt][0], ah[mt][1], ah[mt][2], ah[mt][3], bl0, bl1);
                }
            }
        }
        __syncthreads();
    }

    // store: c[mt][nt] is 16x8; rows grp/grp+8, cols 2tg/2tg+1
#pragma unroll
    for (int mt = 0; mt < 4; mt++) {
#pragma unroll
        for (int nt = 0; nt < 4; nt++) {
            int gcol = col0 + wc * 32 + nt * 8 + 2 * tg;
            if (gcol >= T2) continue;
            float* Csel = (gcol >= M) ? Cp1 : Cp0;
            int gc = (gcol >= M) ? gcol - M : gcol;
            int gr0 = row0 + wr * 64 + mt * 16 + grp;
            if (gr0 < N) {
                float2 v = make_float2(c[mt][nt][0], c[mt][nt][1]);
                *reinterpret_cast<float2*>(Csel + (size_t)gr0 * M + gc) = v;
            }
            int gr1 = gr0 + 8;
            if (gr1 < N) {
                float2 v = make_float2(c[mt][nt][2], c[mt][nt][3]);
                *reinterpret_cast<float2*>(Csel + (size_t)gr1 * M + gc) = v;
            }
        }
    }
}

// ---------------- GATv2: warp per dst node, online softmax, depth-2 prefetch --
template <int V>
__device__ __forceinline__ void load_row(float* d, const float* p) {
    if (V == 4) {
        float4 t = *reinterpret_cast<const float4*>(p);
        d[0] = t.x; d[1] = t.y; d[V > 2 ? 2 : 0] = t.z; d[V > 3 ? 3 : 0] = t.w;
    } else if (V == 2) {
        float2 t = *reinterpret_cast<const float2*>(p);
        d[0] = t.x; d[V > 1 ? 1 : 0] = t.y;
    } else {
        d[0] = p[0];
    }
}

template <int C, bool MEAN>
__global__ void gat_kernel(const float* __restrict__ xl, const float* __restrict__ xr,
                           const float* __restrict__ att, const float* __restrict__ bias,
                           float* __restrict__ out) {
    constexpr int H = HEADS;
    constexpr int HC = H * C;
    constexpr int V = HC / 32;
    int warp = (blockIdx.x * blockDim.x + threadIdx.x) >> 5;
    int lane = threadIdx.x & 31;
    if (warp >= NN) return;
    int node = warp;

    float attv[V], xrv[V], acc[V];
#pragma unroll
    for (int v = 0; v < V; v++) {
        attv[v] = att[lane * V + v];
        xrv[v]  = xr[node * HC + lane * V + v];
        acc[v]  = 0.f;
    }
    float mrun = -CUDART_INF_F, lrun = 0.f;
    int beg = g_off[node], end = g_off[node + 1];

    // depth-2 prefetch ring
    float pre[2][V];
    load_row<V>(pre[0], xl + (size_t)g_srcs[beg] * HC + lane * V);
    if (beg + 1 < end)
        load_row<V>(pre[1], xl + (size_t)g_srcs[beg + 1] * HC + lane * V);
    for (int j = beg; j < end; j++) {
        int slot = (j - beg) & 1;
        float cur[V];
#pragma unroll
        for (int v = 0; v < V; v++) cur[v] = pre[slot][v];
        if (j + 2 < end) {
            int ns = g_srcs[j + 2];
            load_row<V>(pre[slot], xl + (size_t)ns * HC + lane * V);
        }
        float part = 0.f;
#pragma unroll
        for (int v = 0; v < V; v++) {
            float m = cur[v] + xrv[v];
            m = (m > 0.f) ? m : 0.2f * m;
            part = fmaf(attv[v], m, part);
        }
        part += __shfl_xor_sync(0xffffffffu, part, 1);
        part += __shfl_xor_sync(0xffffffffu, part, 2);
        part += __shfl_xor_sync(0xffffffffu, part, 4);
        float e  = part;
        float nm = fmaxf(mrun, e);
        float sc = __expf(mrun - nm);
        float pw = __expf(e - nm);
#pragma unroll
        for (int v = 0; v < V; v++) acc[v] = fmaf(acc[v], sc, pw * cur[v]);
        lrun = fmaf(lrun, sc, pw);
        mrun = nm;
    }
    float inv = 1.f / lrun;
    if (!MEAN) {
#pragma unroll
        for (int v = 0; v < V; v++)
            out[(size_t)node * HC + lane * V + v] = acc[v] * inv + bias[lane * V + v];
    } else {
        float r = acc[0] * inv;
        r += __shfl_xor_sync(0xffffffffu, r, 8);
        r += __shfl_xor_sync(0xffffffffu, r, 16);
        r *= 0.25f;
        if (lane < 8) out[(size_t)node * 8 + lane] = r + bias[lane];
    }
}

// ---------------- GraphNorm (3-kernel, full-grid, deterministic) ----------------
template <int C>
__global__ void gn_part_kernel(const float* __restrict__ x) {
    constexpr int R = 256 / C;
    __shared__ float red[256], red2[256];
    int g = blockIdx.x, sub = blockIdx.y;
    int beg = g_go[g], end = g_go[g + 1];
    int t = threadIdx.x, c = t % C, r = t / C;
    float s = 0.f, q = 0.f;
    for (int i = beg + sub * R + r; i < end; i += NSUB * R) {
        float v = x[(size_t)i * C + c];
        s += v; q = fmaf(v, v, q);
    }
    red[t] = s; red2[t] = q;
    __syncthreads();
    if (t < C) {
        float ss = 0.f, qq = 0.f;
        for (int k = t; k < 256; k += C) { ss += red[k]; qq += red2[k]; }
        g_part[(g * NSUB + sub) * 2 * C + t] = ss;
        g_part[(g * NSUB + sub) * 2 * C + C + t] = qq;
    }
}

template <int C>
__global__ void gn_final_kernel(const float* __restrict__ w, const float* __restrict__ sc) {
    int g = blockIdx.x, c = threadIdx.x;
    int beg = g_go[g], end = g_go[g + 1];
    float cnt = fmaxf((float)(end - beg), 1.f);
    float s = 0.f, q = 0.f;
    for (int sub = 0; sub < NSUB; sub++) {
        s += g_part[(g * NSUB + sub) * 2 * C + c];
        q += g_part[(g * NSUB + sub) * 2 * C + C + c];
    }
    float mu = s / cnt;
    float mus = mu * sc[c];
    float var = q / cnt - 2.f * mus * mu + mus * mus;
    g_mus[g * C + c] = mus;
    g_wr[g * C + c] = w[c] * rsqrtf(var + 1e-5f);
}

template <int C>
__global__ void gn_norm_kernel(const float* __restrict__ x, float* __restrict__ y,
                               const float* __restrict__ b, const int* __restrict__ batch) {
    int i4 = blockIdx.x * blockDim.x + threadIdx.x;
    if (i4 >= NN * C / 4) return;
    int idx = i4 * 4;
    int node = idx / C, c = idx % C;
    int g = batch[node];
    float4 xv = *reinterpret_cast<const float4*>(x + idx);
    float4 mv = *reinterpret_cast<const float4*>(g_mus + g * C + c);
    float4 wv = *reinterpret_cast<const float4*>(g_wr + g * C + c);
    float4 bv = *reinterpret_cast<const float4*>(b + c);
    float4 o;
    o.x = fmaxf(fmaf(xv.x - mv.x, wv.x, bv.x), 0.f);
    o.y = fmaxf(fmaf(xv.y - mv.y, wv.y, bv.y), 0.f);
    o.z = fmaxf(fmaf(xv.z - mv.z, wv.z, bv.z), 0.f);
    o.w = fmaxf(fmaf(xv.w - mv.w, wv.w, bv.w), 0.f);
    *reinterpret_cast<float4*>(y + idx) = o;
}

// ---------------- pool + linear ----------------
__global__ void pool_linear_kernel(const float* __restrict__ h, const float* __restrict__ lw,
                                   const float* __restrict__ lb, float* __restrict__ out) {
    __shared__ float red[256];
    __shared__ float feat[8];
    int g = blockIdx.x;
    int beg = g_go[g], end = g_go[g + 1];
    float fcnt = fmaxf((float)(end - beg), 1.f);
    int t = threadIdx.x;
    int c = t & 7, r = t >> 3;
    float sum = 0.f;
    for (int i = beg + r; i < end; i += 32) sum += h[(size_t)i * 8 + c];
    red[t] = sum; __syncthreads();
    if (t < 8) { float v = 0.f; for (int k = t; k < 256; k += 8) v += red[k]; feat[t] = v / fcnt; }
    __syncthreads();
    if (t < 8) out[NG * 4 + g * 8 + t] = feat[t];   // features after logits block
    if (t < 4) {
        float v = lb[t];
#pragma unroll
        for (int c2 = 0; c2 < 8; c2++) v = fmaf(feat[c2], lw[c2 * 4 + t], v);
        out[g * 4 + t] = v;                          // logits
    }
}

// ---------------- host orchestration ----------------
static void launch_gemm_dual(const float* A, const float* B0, const float* B1,
                             float* C0, float* C1, int N, int K, int M) {
    dim3 grid((2 * M + 127) / 128, (N + 127) / 128);
    gemm_tf32_dual<<<grid, 256>>>(A, B0, B1, C0, C1, N, K, M);
}

template <int C>
static void launch_graphnorm(const float* x, float* y, const float* w, const float* b,
                             const float* s, const int* batch) {
    gn_part_kernel<C><<<dim3(NG, NSUB), 256>>>(x);
    gn_final_kernel<C><<<NG, C>>>(w, s);
    gn_norm_kernel<C><<<(NN * C / 4 + 255) / 256, 256>>>(x, y, b, batch);
}

extern "C" void kernel_launch(void* const* d_in, const int* in_sizes, int n_in,
                              void* d_out, int out_size) {
    const float* x     = (const float*)d_in[0];
    const int*   ei    = (const int*)d_in[1];
    const int*   batch = (const int*)d_in[2];
    const float* w_l1 = (const float*)d_in[3];
    const float* w_r1 = (const float*)d_in[4];
    const float* att1 = (const float*)d_in[5];
    const float* b1   = (const float*)d_in[6];
    const float* gn1w = (const float*)d_in[7];
    const float* gn1b = (const float*)d_in[8];
    const float* gn1s = (const float*)d_in[9];
    const float* w_l2 = (const float*)d_in[10];
    const float* w_r2 = (const float*)d_in[11];
    const float* att2 = (const float*)d_in[12];
    const float* b2   = (const float*)d_in[13];
    const float* gn2w = (const float*)d_in[14];
    const float* gn2b = (const float*)d_in[15];
    const float* gn2s = (const float*)d_in[16];
    const float* w_l3 = (const float*)d_in[17];
    const float* w_r3 = (const float*)d_in[18];
    const float* att3 = (const float*)d_in[19];
    const float* b3   = (const float*)d_in[20];
    const float* gn3w = (const float*)d_in[21];
    const float* gn3b = (const float*)d_in[22];
    const float* gn3s = (const float*)d_in[23];
    const float* linw = (const float*)d_in[24];
    const float* linb = (const float*)d_in[25];
    float* out = (float*)d_out;

    float *xl, *xr, *h1, *h2, *h3;
    cudaGetSymbolAddress((void**)&xl, g_xl);
    cudaGetSymbolAddress((void**)&xr, g_xr);
    cudaGetSymbolAddress((void**)&h1, g_h1);
    cudaGetSymbolAddress((void**)&h2, g_h2);
    cudaGetSymbolAddress((void**)&h3, g_h3);

    // topology (gemm1 interleaved so it lands on the ncu capture slot)
    zero_deg_kernel<<<(NN + 255) / 256, 256>>>();                 // launch 0
    count_deg_kernel<<<(ETOT + 255) / 256, 256>>>(ei);            // launch 1
    scan_kernel<<<1, 1024>>>(batch);                              // launch 2

    // layer 1 GEMM (independent of CSR) — launch 3 = ncu capture target
    launch_gemm_dual(x, w_l1, w_r1, xl, xr, NN, 128, 128);

    scatter_kernel<<<(ETOT + 255) / 256, 256>>>(ei);              // launch 4

    const int GAT_BLOCKS = (NN * 32 + 255) / 256;

    // layer 1: 128 -> 4x32 concat = 128
    gat_kernel<32, false><<<GAT_BLOCKS, 256>>>(xl, xr, att1, b1, h1);
    launch_graphnorm<128>(h1, h1, gn1w, gn1b, gn1s, batch);

    // layer 2: 128 -> 4x16 concat = 64
    launch_gemm_dual(h1, w_l2, w_r2, xl, xr, NN, 128, 64);
    gat_kernel<16, false><<<GAT_BLOCKS, 256>>>(xl, xr, att2, b2, h2);
    launch_graphnorm<64>(h2, h2, gn2w, gn2b, gn2s, batch);

    // layer 3: 64 -> 4x8 mean = 8
    launch_gemm_dual(h2, w_l3, w_r3, xl, xr, NN, 64, 32);
    gat_kernel<8, true><<<GAT_BLOCKS, 256>>>(xl, xr, att3, b3, h3);
    launch_graphnorm<8>(h3, h3, gn3w, gn3b, gn3s, batch);

    // pool + linear: out[0:256] logits, out[256:768] features
    pool_linear_kernel<<<NG, 256>>>(h3, linw, linb, out);
}

// round 7
// speedup vs baseline: 1.2320x; 1.2320x over previous
#include <cuda_runtime.h>
#include <cuda_bf16.h>
#include <math_constants.h>

// Problem constants (fixed by the dataset)
#define NN 50000
#define NE 800000
#define ETOT (NE + NN)       // edges + self loops = 850000
#define NG 64
#define HEADS 4
#define NSUB 8               // GraphNorm sub-partitions per graph

// ---------------- scratch (no cudaMalloc allowed) ----------------
__device__ float g_xl[NN * 128];
__device__ float g_xr[NN * 128];
__device__ float g_h1[NN * 128];
__device__ float g_h2[NN * 64];
__device__ float g_h3[NN * 8];
__device__ int   g_deg[NN];
__device__ int   g_off[NN + 1];
__device__ int   g_cursor[NN];
__device__ int   g_srcs[ETOT];
__device__ int   g_go[NG + 1];
__device__ float g_part[NG * NSUB * 2 * 128];
__device__ float g_mus[NG * 128];
__device__ float g_wr[NG * 128];

// packed bf16x2 hi/lo weight buffers (k-pairs x M), all 6 matrices
// L1: 2 x (64x128)=8192 ; L2: 2 x (64x64)=4096 ; L3: 2 x (32x32)=1024
#define OFF_L1_0 0
#define OFF_L1_1 8192
#define OFF_L2_0 16384
#define OFF_L2_1 20480
#define OFF_L3_0 24576
#define OFF_L3_1 25600
#define BTOT 26624
__device__ unsigned g_bh[BTOT];
__device__ unsigned g_bl[BTOT];

// ---------------- cp.async helpers ----------------
__device__ __forceinline__ void cp_async16(void* smem_ptr, const void* gmem_ptr, bool pred) {
    unsigned saddr = (unsigned)__cvta_generic_to_shared(smem_ptr);
    int sz = pred ? 16 : 0;
    asm volatile("cp.async.ca.shared.global [%0], [%1], 16, %2;\n"
                 :: "r"(saddr), "l"(gmem_ptr), "r"(sz));
}
__device__ __forceinline__ void cp_commit() { asm volatile("cp.async.commit_group;\n"); }
template <int N>
__device__ __forceinline__ void cp_wait() { asm volatile("cp.async.wait_group %0;\n" :: "n"(N)); }

// ---------------- bf16 split helpers ----------------
// pack two floats (v0 -> lower half, v1 -> upper half) as bf16x2, plus residual
__device__ __forceinline__ void split_bf16x2(float v0, float v1, unsigned& hi, unsigned& lo) {
    asm("cvt.rn.bf16x2.f32 %0, %1, %2;" : "=r"(hi) : "f"(v1), "f"(v0));
    float f0 = __uint_as_float(hi << 16);
    float f1 = __uint_as_float(hi & 0xffff0000u);
    asm("cvt.rn.bf16x2.f32 %0, %1, %2;" : "=r"(lo) : "f"(v1 - f1), "f"(v0 - f0));
}

__device__ __forceinline__ void mma_bf16(float c[4], unsigned a0, unsigned a1,
                                         unsigned a2, unsigned a3,
                                         unsigned b0, unsigned b1) {
    asm volatile(
        "mma.sync.aligned.m16n8k16.row.col.f32.bf16.bf16.f32 "
        "{%0,%1,%2,%3}, {%4,%5,%6,%7}, {%8,%9}, {%0,%1,%2,%3};\n"
        : "+f"(c[0]), "+f"(c[1]), "+f"(c[2]), "+f"(c[3])
        : "r"(a0), "r"(a1), "r"(a2), "r"(a3), "r"(b0), "r"(b1));
}

// ---------------- weight pre-split (all 6 matrices, one launch) ----------------
__global__ void split_b_kernel(const float* __restrict__ b10, const float* __restrict__ b11,
                               const float* __restrict__ b20, const float* __restrict__ b21,
                               const float* __restrict__ b30, const float* __restrict__ b31) {
    int i = blockIdx.x * blockDim.x + threadIdx.x;
    if (i >= BTOT) return;
    const float* B; int M, local;
    if (i < OFF_L1_1)      { B = b10; M = 128; local = i; }
    else if (i < OFF_L2_0) { B = b11; M = 128; local = i - OFF_L1_1; }
    else if (i < OFF_L2_1) { B = b20; M = 64;  local = i - OFF_L2_0; }
    else if (i < OFF_L3_0) { B = b21; M = 64;  local = i - OFF_L2_1; }
    else if (i < OFF_L3_1) { B = b30; M = 32;  local = i - OFF_L3_0; }
    else                   { B = b31; M = 32;  local = i - OFF_L3_1; }
    int kp = local / M, n = local % M;
    float v0 = B[(size_t)(2 * kp) * M + n];
    float v1 = B[(size_t)(2 * kp + 1) * M + n];
    unsigned hi, lo;
    split_bf16x2(v0, v1, hi, lo);
    g_bh[i] = hi;
    g_bl[i] = lo;
}

// ---------------- CSR build ----------------
__global__ void zero_deg_kernel() {
    int i = blockIdx.x * blockDim.x + threadIdx.x;
    if (i < NN) g_deg[i] = 0;
}

__global__ void count_deg_kernel(const int* __restrict__ ei) {
    int e = blockIdx.x * blockDim.x + threadIdx.x;
    if (e >= ETOT) return;
    int dst = (e < NE) ? ei[NE + e] : (e - NE);
    atomicAdd(&g_deg[dst], 1);
}

// single-block exclusive scan (warp-shuffle based) + graph offsets
__global__ void scan_kernel(const int* __restrict__ batch) {
    __shared__ int wsum[32];
    __shared__ int carry_s;
    int t = threadIdx.x, lane = t & 31, wid = t >> 5;
    if (t == 0) carry_s = 0;
    __syncthreads();
    for (int base = 0; base < NN; base += 1024) {
        int i = base + t;
        int v = (i < NN) ? g_deg[i] : 0;
        int s = v;
#pragma unroll
        for (int o = 1; o < 32; o <<= 1) {
            int n = __shfl_up_sync(0xffffffffu, s, o);
            if (lane >= o) s += n;
        }
        if (lane == 31) wsum[wid] = s;
        __syncthreads();
        if (wid == 0) {
            int ws = wsum[lane];
#pragma unroll
            for (int o = 1; o < 32; o <<= 1) {
                int n = __shfl_up_sync(0xffffffffu, ws, o);
                if (lane >= o) ws += n;
            }
            wsum[lane] = ws;
        }
        __syncthreads();
        int carry = carry_s;
        int excl = carry + (wid ? wsum[wid - 1] : 0) + s - v;
        if (i < NN) { g_off[i] = excl; g_cursor[i] = excl; }
        int total = wsum[31];
        __syncthreads();
        if (t == 0) carry_s = carry + total;
        __syncthreads();
    }
    if (t == 0) g_off[NN] = carry_s;
    // fused graph offsets (batch is sorted)
    if (t <= NG) {
        if (t == NG) g_go[NG] = NN;
        else {
            int lo = 0, hi = NN;
            while (lo < hi) {
                int mid = (lo + hi) >> 1;
                if (batch[mid] < t) lo = mid + 1; else hi = mid;
            }
            g_go[t] = lo;
        }
    }
}

__global__ void scatter_kernel(const int* __restrict__ ei) {
    int e = blockIdx.x * blockDim.x + threadIdx.x;
    if (e >= ETOT) return;
    int src, dst;
    if (e < NE) { src = ei[e]; dst = ei[NE + e]; }
    else        { src = dst = e - NE; }
    int pos = atomicAdd(&g_cursor[dst], 1);
    g_srcs[pos] = src;
}

// ---------------- 3xBF16 tensor-core GEMM ----------------
// C[N,M] = A[N,K] @ B[K,M], fp32 in/out, near-fp32 accuracy via bf16 hi/lo split.
// B pre-split on device into packed bf16x2 k-pair buffers (g_bh/g_bl).
// Block tile 128x64, 8 warps (4x2), warp tile 32x32, m16n8k16 MMA.
__global__ __launch_bounds__(256) void gemm_bf16_dual(
    const float* __restrict__ A,
    int bOff0, int bOff1,
    float* __restrict__ Cp0, float* __restrict__ Cp1,
    int N, int K, int M) {
    int bOff = blockIdx.z ? bOff1 : bOff0;
    float* C = blockIdx.z ? Cp1 : Cp0;
    const unsigned* Bh = g_bh + bOff;
    const unsigned* Bl = g_bl + bOff;

    __shared__ float    As[2][128][20];  // fp32 A tile; stride 20 conflict-free
    __shared__ unsigned Bsh[2][8][72];   // packed bf16x2 hi, k-pairs x cols
    __shared__ unsigned Bsl[2][8][72];   // packed bf16x2 lo

    int t = threadIdx.x;
    int w = t >> 5, lane = t & 31;
    int wr = w >> 1, wc = w & 1;         // 4x2 warp grid
    int grp = lane >> 2, tg = lane & 3;
    int row0 = blockIdx.y * 128;
    int col0 = blockIdx.x * 64;

    float c[2][4][4];
#pragma unroll
    for (int i = 0; i < 2; i++)
#pragma unroll
        for (int j = 0; j < 4; j++)
#pragma unroll
            for (int k = 0; k < 4; k++) c[i][j][k] = 0.f;

    auto load_tiles = [&](int stage, int kt) {
        int k0 = kt << 4;
        // A tile 128x16 = 512 float4, 2 per thread
#pragma unroll
        for (int i = t; i < 512; i += 256) {
            int r = i >> 2, c4 = (i & 3) * 4;
            bool p = (row0 + r) < N;
            const float* src = p ? (A + (size_t)(row0 + r) * K + k0 + c4) : A;
            cp_async16(&As[stage][r][c4], src, p);
        }
        // B hi+lo tiles: 8 k-pairs x 64 cols u32 each = 128 float4 each; 1 f4/thread
        {
            int buf = t >> 7;            // 0 = hi, 1 = lo
            int rem = t & 127;
            int r = rem >> 4, c4 = (rem & 15) * 4;
            bool p = (col0 + c4) < M;
            const unsigned* Bsel = buf ? Bl : Bh;
            const unsigned* src = p ? (Bsel + (size_t)(kt * 8 + r) * M + col0 + c4) : Bh;
            unsigned* dst = buf ? &Bsl[stage][r][c4] : &Bsh[stage][r][c4];
            cp_async16(dst, src, p);
        }
    };

    int KT = K >> 4;
    load_tiles(0, 0);
    cp_commit();

    for (int kt = 0; kt < KT; kt++) {
        int cur = kt & 1;
        if (kt + 1 < KT) {
            load_tiles(cur ^ 1, kt + 1);
            cp_commit();
            cp_wait<1>();
        } else {
            cp_wait<0>();
        }
        __syncthreads();

        // A fragments: split fp32 pairs -> bf16x2 hi/lo
        unsigned ah[2][4], al[2][4];
#pragma unroll
        for (int mt = 0; mt < 2; mt++) {
            int r0 = wr * 32 + mt * 16;
            float2 p0 = *reinterpret_cast<const float2*>(&As[cur][r0 + grp][2 * tg]);
            float2 p1 = *reinterpret_cast<const float2*>(&As[cur][r0 + grp + 8][2 * tg]);
            float2 p2 = *reinterpret_cast<const float2*>(&As[cur][r0 + grp][2 * tg + 8]);
            float2 p3 = *reinterpret_cast<const float2*>(&As[cur][r0 + grp + 8][2 * tg + 8]);
            split_bf16x2(p0.x, p0.y, ah[mt][0], al[mt][0]);
            split_bf16x2(p1.x, p1.y, ah[mt][1], al[mt][1]);
            split_bf16x2(p2.x, p2.y, ah[mt][2], al[mt][2]);
            split_bf16x2(p3.x, p3.y, ah[mt][3], al[mt][3]);
        }
#pragma unroll
        for (int nt = 0; nt < 4; nt++) {
            int ci = wc * 32 + nt * 8 + grp;
            unsigned bh0 = Bsh[cur][tg][ci];
            unsigned bh1 = Bsh[cur][tg + 4][ci];
            unsigned bl0 = Bsl[cur][tg][ci];
            unsigned bl1 = Bsl[cur][tg + 4][ci];
#pragma unroll
            for (int mt = 0; mt < 2; mt++) {
                mma_bf16(c[mt][nt], ah[mt][0], ah[mt][1], ah[mt][2], ah[mt][3], bh0, bh1);
                mma_bf16(c[mt][nt], al[mt][0], al[mt][1], al[mt][2], al[mt][3], bh0, bh1);
                mma_bf16(c[mt][nt], ah[mt][0], ah[mt][1], ah[mt][2], ah[mt][3], bl0, bl1);
            }
        }
        __syncthreads();
    }

    // store: c[mt][nt] is 16x8; rows grp/grp+8, cols 2tg/2tg+1
#pragma unroll
    for (int mt = 0; mt < 2; mt++) {
#pragma unroll
        for (int nt = 0; nt < 4; nt++) {
            int gc = col0 + wc * 32 + nt * 8 + 2 * tg;
            if (gc >= M) continue;
            int gr0 = row0 + wr * 32 + mt * 16 + grp;
            if (gr0 < N) {
                float2 v = make_float2(c[mt][nt][0], c[mt][nt][1]);
                *reinterpret_cast<float2*>(C + (size_t)gr0 * M + gc) = v;
            }
            int gr1 = gr0 + 8;
            if (gr1 < N) {
                float2 v = make_float2(c[mt][nt][2], c[mt][nt][3]);
                *reinterpret_cast<float2*>(C + (size_t)gr1 * M + gc) = v;
            }
        }
    }
}

// ---------------- GATv2: warp per dst node, online softmax, depth-1 prefetch --
template <int V>
__device__ __forceinline__ void load_row(float* d, const float* p) {
    if (V == 4) {
        float4 t = *reinterpret_cast<const float4*>(p);
        d[0] = t.x; d[1] = t.y; d[V > 2 ? 2 : 0] = t.z; d[V > 3 ? 3 : 0] = t.w;
    } else if (V == 2) {
        float2 t = *reinterpret_cast<const float2*>(p);
        d[0] = t.x; d[V > 1 ? 1 : 0] = t.y;
    } else {
        d[0] = p[0];
    }
}

template <int C, bool MEAN>
__global__ void gat_kernel(const float* __restrict__ xl, const float* __restrict__ xr,
                           const float* __restrict__ att, const float* __restrict__ bias,
                           float* __restrict__ out) {
    constexpr int H = HEADS;
    constexpr int HC = H * C;
    constexpr int V = HC / 32;
    int warp = (blockIdx.x * blockDim.x + threadIdx.x) >> 5;
    int lane = threadIdx.x & 31;
    if (warp >= NN) return;
    int node = warp;

    float attv[V], xrv[V], acc[V];
#pragma unroll
    for (int v = 0; v < V; v++) {
        attv[v] = att[lane * V + v];
        xrv[v]  = xr[node * HC + lane * V + v];
        acc[v]  = 0.f;
    }
    float mrun = -CUDART_INF_F, lrun = 0.f;
    int beg = g_off[node], end = g_off[node + 1];

    // software pipeline: prefetch next src row while computing current
    float nxt[V];
    load_row<V>(nxt, xl + (size_t)g_srcs[beg] * HC + lane * V);
    for (int j = beg; j < end; j++) {
        float cur[V];
#pragma unroll
        for (int v = 0; v < V; v++) cur[v] = nxt[v];
        if (j + 1 < end) {
            int ns = g_srcs[j + 1];
            load_row<V>(nxt, xl + (size_t)ns * HC + lane * V);
        }
        float part = 0.f;
#pragma unroll
        for (int v = 0; v < V; v++) {
            float m = cur[v] + xrv[v];
            m = (m > 0.f) ? m : 0.2f * m;
            part = fmaf(attv[v], m, part);
        }
        part += __shfl_xor_sync(0xffffffffu, part, 1);
        part += __shfl_xor_sync(0xffffffffu, part, 2);
        part += __shfl_xor_sync(0xffffffffu, part, 4);
        float e  = part;
        float nm = fmaxf(mrun, e);
        float sc = __expf(mrun - nm);
        float pw = __expf(e - nm);
#pragma unroll
        for (int v = 0; v < V; v++) acc[v] = fmaf(acc[v], sc, pw * cur[v]);
        lrun = fmaf(lrun, sc, pw);
        mrun = nm;
    }
    float inv = 1.f / lrun;
    if (!MEAN) {
#pragma unroll
        for (int v = 0; v < V; v++)
            out[(size_t)node * HC + lane * V + v] = acc[v] * inv + bias[lane * V + v];
    } else {
        float r = acc[0] * inv;
        r += __shfl_xor_sync(0xffffffffu, r, 8);
        r += __shfl_xor_sync(0xffffffffu, r, 16);
        r *= 0.25f;
        if (lane < 8) out[(size_t)node * 8 + lane] = r + bias[lane];
    }
}

// ---------------- GraphNorm (3-kernel, full-grid, deterministic) ----------------
template <int C>
__global__ void gn_part_kernel(const float* __restrict__ x) {
    constexpr int R = 256 / C;
    __shared__ float red[256], red2[256];
    int g = blockIdx.x, sub = blockIdx.y;
    int beg = g_go[g], end = g_go[g + 1];
    int t = threadIdx.x, c = t % C, r = t / C;
    float s = 0.f, q = 0.f;
    for (int i = beg + sub * R + r; i < end; i += NSUB * R) {
        float v = x[(size_t)i * C + c];
        s += v; q = fmaf(v, v, q);
    }
    red[t] = s; red2[t] = q;
    __syncthreads();
    if (t < C) {
        float ss = 0.f, qq = 0.f;
        for (int k = t; k < 256; k += C) { ss += red[k]; qq += red2[k]; }
        g_part[(g * NSUB + sub) * 2 * C + t] = ss;
        g_part[(g * NSUB + sub) * 2 * C + C + t] = qq;
    }
}

template <int C>
__global__ void gn_final_kernel(const float* __restrict__ w, const float* __restrict__ sc) {
    int g = blockIdx.x, c = threadIdx.x;
    int beg = g_go[g], end = g_go[g + 1];
    float cnt = fmaxf((float)(end - beg), 1.f);
    float s = 0.f, q = 0.f;
    for (int sub = 0; sub < NSUB; sub++) {
        s += g_part[(g * NSUB + sub) * 2 * C + c];
        q += g_part[(g * NSUB + sub) * 2 * C + C + c];
    }
    float mu = s / cnt;
    float mus = mu * sc[c];
    float var = q / cnt - 2.f * mus * mu + mus * mus;
    g_mus[g * C + c] = mus;
    g_wr[g * C + c] = w[c] * rsqrtf(var + 1e-5f);
}

template <int C>
__global__ void gn_norm_kernel(const float* __restrict__ x, float* __restrict__ y,
                               const float* __restrict__ b, const int* __restrict__ batch) {
    int i4 = blockIdx.x * blockDim.x + threadIdx.x;
    if (i4 >= NN * C / 4) return;
    int idx = i4 * 4;
    int node = idx / C, c = idx % C;
    int g = batch[node];
    float4 xv = *reinterpret_cast<const float4*>(x + idx);
    float4 mv = *reinterpret_cast<const float4*>(g_mus + g * C + c);
    float4 wv = *reinterpret_cast<const float4*>(g_wr + g * C + c);
    float4 bv = *reinterpret_cast<const float4*>(b + c);
    float4 o;
    o.x = fmaxf(fmaf(xv.x - mv.x, wv.x, bv.x), 0.f);
    o.y = fmaxf(fmaf(xv.y - mv.y, wv.y, bv.y), 0.f);
    o.z = fmaxf(fmaf(xv.z - mv.z, wv.z, bv.z), 0.f);
    o.w = fmaxf(fmaf(xv.w - mv.w, wv.w, bv.w), 0.f);
    *reinterpret_cast<float4*>(y + idx) = o;
}

// ---------------- pool + linear ----------------
__global__ void pool_linear_kernel(const float* __restrict__ h, const float* __restrict__ lw,
                                   const float* __restrict__ lb, float* __restrict__ out) {
    __shared__ float red[256];
    __shared__ float feat[8];
    int g = blockIdx.x;
    int beg = g_go[g], end = g_go[g + 1];
    float fcnt = fmaxf((float)(end - beg), 1.f);
    int t = threadIdx.x;
    int c = t & 7, r = t >> 3;
    float sum = 0.f;
    for (int i = beg + r; i < end; i += 32) sum += h[(size_t)i * 8 + c];
    red[t] = sum; __syncthreads();
    if (t < 8) { float v = 0.f; for (int k = t; k < 256; k += 8) v += red[k]; feat[t] = v / fcnt; }
    __syncthreads();
    if (t < 8) out[NG * 4 + g * 8 + t] = feat[t];   // features after logits block
    if (t < 4) {
        float v = lb[t];
#pragma unroll
        for (int c2 = 0; c2 < 8; c2++) v = fmaf(feat[c2], lw[c2 * 4 + t], v);
        out[g * 4 + t] = v;                          // logits
    }
}

// ---------------- host orchestration ----------------
static void launch_gemm_dual(const float* A, int bOff0, int bOff1,
                             float* C0, float* C1, int N, int K, int M) {
    dim3 grid((M + 63) / 64, (N + 127) / 128, 2);
    gemm_bf16_dual<<<grid, 256>>>(A, bOff0, bOff1, C0, C1, N, K, M);
}

template <int C>
static void launch_graphnorm(const float* x, float* y, const float* w, const float* b,
                             const float* s, const int* batch) {
    gn_part_kernel<C><<<dim3(NG, NSUB), 256>>>(x);
    gn_final_kernel<C><<<NG, C>>>(w, s);
    gn_norm_kernel<C><<<(NN * C / 4 + 255) / 256, 256>>>(x, y, b, batch);
}

extern "C" void kernel_launch(void* const* d_in, const int* in_sizes, int n_in,
                              void* d_out, int out_size) {
    const float* x     = (const float*)d_in[0];
    const int*   ei    = (const int*)d_in[1];
    const int*   batch = (const int*)d_in[2];
    const float* w_l1 = (const float*)d_in[3];
    const float* w_r1 = (const float*)d_in[4];
    const float* att1 = (const float*)d_in[5];
    const float* b1   = (const float*)d_in[6];
    const float* gn1w = (const float*)d_in[7];
    const float* gn1b = (const float*)d_in[8];
    const float* gn1s = (const float*)d_in[9];
    const float* w_l2 = (const float*)d_in[10];
    const float* w_r2 = (const float*)d_in[11];
    const float* att2 = (const float*)d_in[12];
    const float* b2   = (const float*)d_in[13];
    const float* gn2w = (const float*)d_in[14];
    const float* gn2b = (const float*)d_in[15];
    const float* gn2s = (const float*)d_in[16];
    const float* w_l3 = (const float*)d_in[17];
    const float* w_r3 = (const float*)d_in[18];
    const float* att3 = (const float*)d_in[19];
    const float* b3   = (const float*)d_in[20];
    const float* gn3w = (const float*)d_in[21];
    const float* gn3b = (const float*)d_in[22];
    const float* gn3s = (const float*)d_in[23];
    const float* linw = (const float*)d_in[24];
    const float* linb = (const float*)d_in[25];
    float* out = (float*)d_out;

    float *xl, *xr, *h1, *h2, *h3;
    cudaGetSymbolAddress((void**)&xl, g_xl);
    cudaGetSymbolAddress((void**)&xr, g_xr);
    cudaGetSymbolAddress((void**)&h1, g_h1);
    cudaGetSymbolAddress((void**)&h2, g_h2);
    cudaGetSymbolAddress((void**)&h3, g_h3);

    // launch order keeps the layer-1 GEMM at slot 3 (ncu capture target)
    zero_deg_kernel<<<(NN + 255) / 256, 256>>>();                         // 0
    count_deg_kernel<<<(ETOT + 255) / 256, 256>>>(ei);                    // 1
    split_b_kernel<<<(BTOT + 255) / 256, 256>>>(w_l1, w_r1, w_l2, w_r2,
                                                w_l3, w_r3);              // 2
    launch_gemm_dual(x, OFF_L1_0, OFF_L1_1, xl, xr, NN, 128, 128);        // 3 (capture)
    scan_kernel<<<1, 1024>>>(batch);                                      // 4
    scatter_kernel<<<(ETOT + 255) / 256, 256>>>(ei);                      // 5

    const int GAT_BLOCKS = (NN * 32 + 255) / 256;

    // layer 1: 128 -> 4x32 concat = 128
    gat_kernel<32, false><<<GAT_BLOCKS, 256>>>(xl, xr, att1, b1, h1);
    launch_graphnorm<128>(h1, h1, gn1w, gn1b, gn1s, batch);

    // layer 2: 128 -> 4x16 concat = 64
    launch_gemm_dual(h1, OFF_L2_0, OFF_L2_1, xl, xr, NN, 128, 64);
    gat_kernel<16, false><<<GAT_BLOCKS, 256>>>(xl, xr, att2, b2, h2);
    launch_graphnorm<64>(h2, h2, gn2w, gn2b, gn2s, batch);

    // layer 3: 64 -> 4x8 mean = 8
    launch_gemm_dual(h2, OFF_L3_0, OFF_L3_1, xl, xr, NN, 64, 32);
    gat_kernel<8, true><<<GAT_BLOCKS, 256>>>(xl, xr, att3, b3, h3);
    launch_graphnorm<8>(h3, h3, gn3w, gn3b, gn3s, batch);

    // pool + linear: out[0:256] logits, out[256:768] features
    pool_linear_kernel<<<NG, 256>>>(h3, linw, linb, out);
}

// round 9
// speedup vs baseline: 1.2871x; 1.0447x over previous
#include <cuda_runtime.h>
#include <cuda_bf16.h>
#include <math_constants.h>

// Problem constants (fixed by the dataset)
#define NN 50000
#define NE 800000
#define ETOT (NE + NN)       // edges + self loops = 850000
#define NG 64
#define HEADS 4
#define NSUB 8               // GraphNorm sub-partitions per graph

// ---------------- scratch (no cudaMalloc allowed) ----------------
__device__ float g_xl[NN * 128];
__device__ float g_xr[NN * 128];
__device__ float g_h1[NN * 128];
__device__ float g_h2[NN * 64];
__device__ float g_h3[NN * 8];
__device__ int   g_deg[NN];
__device__ int   g_off[NN + 1];
__device__ int   g_cursor[NN];
__device__ int   g_srcs[ETOT];
__device__ int   g_go[NG + 1];
__device__ float g_part[NG * NSUB * 2 * 128];
__device__ float g_mus[NG * 128];
__device__ float g_wr[NG * 128];

// packed bf16x2 hi/lo weight buffers (k-pairs x M), all 6 matrices
#define OFF_L1_0 0
#define OFF_L1_1 8192
#define OFF_L2_0 16384
#define OFF_L2_1 20480
#define OFF_L3_0 24576
#define OFF_L3_1 25600
#define BTOT 26624
__device__ unsigned g_bh[BTOT];
__device__ unsigned g_bl[BTOT];

// ---------------- cp.async helpers ----------------
__device__ __forceinline__ void cp_async16(void* smem_ptr, const void* gmem_ptr, bool pred) {
    unsigned saddr = (unsigned)__cvta_generic_to_shared(smem_ptr);
    int sz = pred ? 16 : 0;
    asm volatile("cp.async.ca.shared.global [%0], [%1], 16, %2;\n"
                 :: "r"(saddr), "l"(gmem_ptr), "r"(sz));
}
__device__ __forceinline__ void cp_commit() { asm volatile("cp.async.commit_group;\n"); }
template <int N>
__device__ __forceinline__ void cp_wait() { asm volatile("cp.async.wait_group %0;\n" :: "n"(N)); }

// ---------------- bf16 split helpers ----------------
__device__ __forceinline__ void split_bf16x2(float v0, float v1, unsigned& hi, unsigned& lo) {
    asm("cvt.rn.bf16x2.f32 %0, %1, %2;" : "=r"(hi) : "f"(v1), "f"(v0));
    float f0 = __uint_as_float(hi << 16);
    float f1 = __uint_as_float(hi & 0xffff0000u);
    asm("cvt.rn.bf16x2.f32 %0, %1, %2;" : "=r"(lo) : "f"(v1 - f1), "f"(v0 - f0));
}

__device__ __forceinline__ void mma_bf16(float c[4], unsigned a0, unsigned a1,
                                         unsigned a2, unsigned a3,
                                         unsigned b0, unsigned b1) {
    asm volatile(
        "mma.sync.aligned.m16n8k16.row.col.f32.bf16.bf16.f32 "
        "{%0,%1,%2,%3}, {%4,%5,%6,%7}, {%8,%9}, {%0,%1,%2,%3};\n"
        : "+f"(c[0]), "+f"(c[1]), "+f"(c[2]), "+f"(c[3])
        : "r"(a0), "r"(a1), "r"(a2), "r"(a3), "r"(b0), "r"(b1));
}

// ---------------- weight pre-split (all 6 matrices, one launch) ----------------
__global__ void split_b_kernel(const float* __restrict__ b10, const float* __restrict__ b11,
                               const float* __restrict__ b20, const float* __restrict__ b21,
                               const float* __restrict__ b30, const float* __restrict__ b31) {
    int i = blockIdx.x * blockDim.x + threadIdx.x;
    if (i >= BTOT) return;
    const float* B; int M, local;
    if (i < OFF_L1_1)      { B = b10; M = 128; local = i; }
    else if (i < OFF_L2_0) { B = b11; M = 128; local = i - OFF_L1_1; }
    else if (i < OFF_L2_1) { B = b20; M = 64;  local = i - OFF_L2_0; }
    else if (i < OFF_L3_0) { B = b21; M = 64;  local = i - OFF_L2_1; }
    else if (i < OFF_L3_1) { B = b30; M = 32;  local = i - OFF_L3_0; }
    else                   { B = b31; M = 32;  local = i - OFF_L3_1; }
    int kp = local / M, n = local % M;
    float v0 = B[(size_t)(2 * kp) * M + n];
    float v1 = B[(size_t)(2 * kp + 1) * M + n];
    unsigned hi, lo;
    split_bf16x2(v0, v1, hi, lo);
    g_bh[i] = hi;
    g_bl[i] = lo;
}

// ---------------- CSR build ----------------
__global__ void zero_deg_kernel() {
    int i = blockIdx.x * blockDim.x + threadIdx.x;
    if (i < NN) g_deg[i] = 0;
}

__global__ void count_deg_kernel(const int* __restrict__ ei) {
    int e = blockIdx.x * blockDim.x + threadIdx.x;
    if (e >= ETOT) return;
    int dst = (e < NE) ? ei[NE + e] : (e - NE);
    atomicAdd(&g_deg[dst], 1);
}

// single-block exclusive scan (warp-shuffle based) + graph offsets
__global__ void scan_kernel(const int* __restrict__ batch) {
    __shared__ int wsum[32];
    __shared__ int carry_s;
    int t = threadIdx.x, lane = t & 31, wid = t >> 5;
    if (t == 0) carry_s = 0;
    __syncthreads();
    for (int base = 0; base < NN; base += 1024) {
        int i = base + t;
        int v = (i < NN) ? g_deg[i] : 0;
        int s = v;
#pragma unroll
        for (int o = 1; o < 32; o <<= 1) {
            int n = __shfl_up_sync(0xffffffffu, s, o);
            if (lane >= o) s += n;
        }
        if (lane == 31) wsum[wid] = s;
        __syncthreads();
        if (wid == 0) {
            int ws = wsum[lane];
#pragma unroll
            for (int o = 1; o < 32; o <<= 1) {
                int n = __shfl_up_sync(0xffffffffu, ws, o);
                if (lane >= o) ws += n;
            }
            wsum[lane] = ws;
        }
        __syncthreads();
        int carry = carry_s;
        int excl = carry + (wid ? wsum[wid - 1] : 0) + s - v;
        if (i < NN) { g_off[i] = excl; g_cursor[i] = excl; }
        int total = wsum[31];
        __syncthreads();
        if (t == 0) carry_s = carry + total;
        __syncthreads();
    }
    if (t == 0) g_off[NN] = carry_s;
    if (t <= NG) {
        if (t == NG) g_go[NG] = NN;
        else {
            int lo = 0, hi = NN;
            while (lo < hi) {
                int mid = (lo + hi) >> 1;
                if (batch[mid] < t) lo = mid + 1; else hi = mid;
            }
            g_go[t] = lo;
        }
    }
}

__global__ void scatter_kernel(const int* __restrict__ ei) {
    int e = blockIdx.x * blockDim.x + threadIdx.x;
    if (e >= ETOT) return;
    int src, dst;
    if (e < NE) { src = ei[e]; dst = ei[NE + e]; }
    else        { src = dst = e - NE; }
    int pos = atomicAdd(&g_cursor[dst], 1);
    g_srcs[pos] = src;
}

// ---------------- 3xBF16 tensor-core GEMM (A split at STS time) ----------------
// C[N,M] = A[N,K] @ B[K,M]. A: LDG float4 -> split -> STS packed bf16x2 hi/lo.
// B pre-split on device (g_bh/g_bl), loaded via cp.async.
// Block tile 128x64, 8 warps (4x2), warp tile 32x32, m16n8k16 MMA.
__global__ __launch_bounds__(256) void gemm_bf16_dual(
    const float* __restrict__ A,
    int bOff0, int bOff1,
    float* __restrict__ Cp0, float* __restrict__ Cp1,
    int N, int K, int M) {
    int bOff = blockIdx.z ? bOff1 : bOff0;
    float* C = blockIdx.z ? Cp1 : Cp0;
    const unsigned* Bh = g_bh + bOff;
    const unsigned* Bl = g_bl + bOff;

    __shared__ unsigned Ash[2][8][136];  // [kpair][row], stride 136 (≡8 mod 32)
    __shared__ unsigned Asl[2][8][136];
    __shared__ unsigned Bsh[2][8][72];   // [kpair][col]
    __shared__ unsigned Bsl[2][8][72];

    int t = threadIdx.x;
    int w = t >> 5, lane = t & 31;
    int wr = w >> 1, wc = w & 1;         // 4x2 warp grid
    int grp = lane >> 2, tg = lane & 3;
    int row0 = blockIdx.y * 128;
    int col0 = blockIdx.x * 64;

    // A loader indices: 2 float4 per thread per ktile
    int ar0 = t >> 1;                    // rows t/2 and t/2+... use i>>2 mapping
    (void)ar0;

    float c[2][4][4];
#pragma unroll
    for (int i = 0; i < 2; i++)
#pragma unroll
        for (int j = 0; j < 4; j++)
#pragma unroll
            for (int k = 0; k < 4; k++) c[i][j][k] = 0.f;

    float4 areg[2];

    auto lda_regs = [&](int kt) {
        int k0 = kt << 4;
#pragma unroll
        for (int u = 0; u < 2; u++) {
            int i = t + u * 256;
            int r = i >> 2, c4 = (i & 3) * 4;
            if (row0 + r < N)
                areg[u] = *reinterpret_cast<const float4*>(A + (size_t)(row0 + r) * K + k0 + c4);
            else
                areg[u] = make_float4(0.f, 0.f, 0.f, 0.f);
        }
    };
    auto sts_a = [&](int stage) {
#pragma unroll
        for (int u = 0; u < 2; u++) {
            int i = t + u * 256;
            int r = i >> 2, kp = (i & 3) * 2;
            unsigned h0, l0, h1, l1;
            split_bf16x2(areg[u].x, areg[u].y, h0, l0);
            split_bf16x2(areg[u].z, areg[u].w, h1, l1);
            Ash[stage][kp][r] = h0; Ash[stage][kp + 1][r] = h1;
            Asl[stage][kp][r] = l0; Asl[stage][kp + 1][r] = l1;
        }
    };
    auto ldb_async = [&](int stage, int kt) {
        int buf = t >> 7;                // 0 = hi, 1 = lo
        int rem = t & 127;
        int r = rem >> 4, c4 = (rem & 15) * 4;
        bool p = (col0 + c4) < M;
        const unsigned* Bsel = buf ? Bl : Bh;
        const unsigned* src = p ? (Bsel + (size_t)(kt * 8 + r) * M + col0 + c4) : Bh;
        unsigned* dst = buf ? &Bsl[stage][r][c4] : &Bsh[stage][r][c4];
        cp_async16(dst, src, p);
    };

    int KT = K >> 4;
    lda_regs(0);
    ldb_async(0, 0);
    cp_commit();
    sts_a(0);

    for (int kt = 0; kt < KT; kt++) {
        int cur = kt & 1;
        if (kt + 1 < KT) {
            lda_regs(kt + 1);            // overlap LDG with compute below
            ldb_async(cur ^ 1, kt + 1);
            cp_commit();
            cp_wait<1>();
        } else {
            cp_wait<0>();
        }
        __syncthreads();                 // stage `cur` fully ready

        unsigned ah[2][4], al[2][4];
#pragma unroll
        for (int mt = 0; mt < 2; mt++) {
            int r0 = wr * 32 + mt * 16;
            ah[mt][0] = Ash[cur][tg][r0 + grp];
            ah[mt][1] = Ash[cur][tg][r0 + grp + 8];
            ah[mt][2] = Ash[cur][tg + 4][r0 + grp];
            ah[mt][3] = Ash[cur][tg + 4][r0 + grp + 8];
            al[mt][0] = Asl[cur][tg][r0 + grp];
            al[mt][1] = Asl[cur][tg][r0 + grp + 8];
            al[mt][2] = Asl[cur][tg + 4][r0 + grp];
            al[mt][3] = Asl[cur][tg + 4][r0 + grp + 8];
        }
#pragma unroll
        for (int nt = 0; nt < 4; nt++) {
            int ci = wc * 32 + nt * 8 + grp;
            unsigned bh0 = Bsh[cur][tg][ci];
            unsigned bh1 = Bsh[cur][tg + 4][ci];
            unsigned bl0 = Bsl[cur][tg][ci];
            unsigned bl1 = Bsl[cur][tg + 4][ci];
#pragma unroll
            for (int mt = 0; mt < 2; mt++) {
                mma_bf16(c[mt][nt], ah[mt][0], ah[mt][1], ah[mt][2], ah[mt][3], bh0, bh1);
                mma_bf16(c[mt][nt], al[mt][0], al[mt][1], al[mt][2], al[mt][3], bh0, bh1);
                mma_bf16(c[mt][nt], ah[mt][0], ah[mt][1], ah[mt][2], ah[mt][3], bl0, bl1);
            }
        }
        if (kt + 1 < KT) sts_a(cur ^ 1); // safe: stage cur^1 not read this iter
        __syncthreads();
    }

    // store: c[mt][nt] is 16x8; rows grp/grp+8, cols 2tg/2tg+1
#pragma unroll
    for (int mt = 0; mt < 2; mt++) {
#pragma unroll
        for (int nt = 0; nt < 4; nt++) {
            int gc = col0 + wc * 32 + nt * 8 + 2 * tg;
            if (gc >= M) continue;
            int gr0 = row0 + wr * 32 + mt * 16 + grp;
            if (gr0 < N) {
                float2 v = make_float2(c[mt][nt][0], c[mt][nt][1]);
                *reinterpret_cast<float2*>(C + (size_t)gr0 * M + gc) = v;
            }
            int gr1 = gr0 + 8;
            if (gr1 < N) {
                float2 v = make_float2(c[mt][nt][2], c[mt][nt][3]);
                *reinterpret_cast<float2*>(C + (size_t)gr1 * M + gc) = v;
            }
        }
    }
}

// ---------------- GATv2: warp per dst node, online softmax, 2-edge unroll ----
template <int V>
__device__ __forceinline__ void load_row(float* d, const float* p) {
    if (V == 4) {
        float4 t = *reinterpret_cast<const float4*>(p);
        d[0] = t.x; d[1] = t.y; d[V > 2 ? 2 : 0] = t.z; d[V > 3 ? 3 : 0] = t.w;
    } else if (V == 2) {
        float2 t = *reinterpret_cast<const float2*>(p);
        d[0] = t.x; d[V > 1 ? 1 : 0] = t.y;
    } else {
        d[0] = p[0];
    }
}

template <int V>
__device__ __forceinline__ float edge_score(const float* cur, const float* xrv,
                                            const float* attv) {
    float part = 0.f;
#pragma unroll
    for (int v = 0; v < V; v++) {
        float m = cur[v] + xrv[v];
        m = (m > 0.f) ? m : 0.2f * m;
        part = fmaf(attv[v], m, part);
    }
    part += __shfl_xor_sync(0xffffffffu, part, 1);
    part += __shfl_xor_sync(0xffffffffu, part, 2);
    part += __shfl_xor_sync(0xffffffffu, part, 4);
    return part;
}

template <int C, bool MEAN>
__global__ void gat_kernel(const float* __restrict__ xl, const float* __restrict__ xr,
                           const float* __restrict__ att, const float* __restrict__ bias,
                           float* __restrict__ out) {
    constexpr int H = HEADS;
    constexpr int HC = H * C;
    constexpr int V = HC / 32;
    int warp = (blockIdx.x * blockDim.x + threadIdx.x) >> 5;
    int lane = threadIdx.x & 31;
    if (warp >= NN) return;
    int node = warp;

    float attv[V], xrv[V], acc[V];
#pragma unroll
    for (int v = 0; v < V; v++) {
        attv[v] = att[lane * V + v];
        xrv[v]  = xr[node * HC + lane * V + v];
        acc[v]  = 0.f;
    }
    float mrun = -CUDART_INF_F, lrun = 0.f;
    int beg = g_off[node], end = g_off[node + 1];

    // two independent prefetch slots (explicit regs, compile-time indices)
    float p0[V], p1[V];
    load_row<V>(p0, xl + (size_t)g_srcs[beg] * HC + lane * V);
    if (beg + 1 < end)
        load_row<V>(p1, xl + (size_t)g_srcs[beg + 1] * HC + lane * V);

    int j = beg;
    for (; j + 2 <= end; j += 2) {
        float c0[V], c1[V];
#pragma unroll
        for (int v = 0; v < V; v++) { c0[v] = p0[v]; c1[v] = p1[v]; }
        if (j + 2 < end)
            load_row<V>(p0, xl + (size_t)g_srcs[j + 2] * HC + lane * V);
        if (j + 3 < end)
            load_row<V>(p1, xl + (size_t)g_srcs[j + 3] * HC + lane * V);

        float e0 = edge_score<V>(c0, xrv, attv);
        float e1 = edge_score<V>(c1, xrv, attv);
        float nm = fmaxf(mrun, fmaxf(e0, e1));
        float sc = __expf(mrun - nm);
        float w0 = __expf(e0 - nm);
        float w1 = __expf(e1 - nm);
#pragma unroll
        for (int v = 0; v < V; v++)
            acc[v] = fmaf(acc[v], sc, fmaf(w0, c0[v], w1 * c1[v]));
        lrun = fmaf(lrun, sc, w0 + w1);
        mrun = nm;
    }
    if (j < end) {  // odd tail: even offset -> lives in p0
        float e0 = edge_score<V>(p0, xrv, attv);
        float nm = fmaxf(mrun, e0);
        float sc = __expf(mrun - nm);
        float w0 = __expf(e0 - nm);
#pragma unroll
        for (int v = 0; v < V; v++) acc[v] = fmaf(acc[v], sc, w0 * p0[v]);
        lrun = fmaf(lrun, sc, w0);
        mrun = nm;
    }

    float inv = 1.f / lrun;
    if (!MEAN) {
#pragma unroll
        for (int v = 0; v < V; v++)
            out[(size_t)node * HC + lane * V + v] = acc[v] * inv + bias[lane * V + v];
    } else {
        float r = acc[0] * inv;
        r += __shfl_xor_sync(0xffffffffu, r, 8);
        r += __shfl_xor_sync(0xffffffffu, r, 16);
        r *= 0.25f;
        if (lane < 8) out[(size_t)node * 8 + lane] = r + bias[lane];
    }
}

// ---------------- GraphNorm (3-kernel, full-grid, deterministic) ----------------
template <int C>
__global__ void gn_part_kernel(const float* __restrict__ x) {
    constexpr int R = 256 / C;
    __shared__ float red[256], red2[256];
    int g = blockIdx.x, sub = blockIdx.y;
    int beg = g_go[g], end = g_go[g + 1];
    int t = threadIdx.x, c = t % C, r = t / C;
    float s = 0.f, q = 0.f;
    for (int i = beg + sub * R + r; i < end; i += NSUB * R) {
        float v = x[(size_t)i * C + c];
        s += v; q = fmaf(v, v, q);
    }
    red[t] = s; red2[t] = q;
    __syncthreads();
    if (t < C) {
        float ss = 0.f, qq = 0.f;
        for (int k = t; k < 256; k += C) { ss += red[k]; qq += red2[k]; }
        g_part[(g * NSUB + sub) * 2 * C + t] = ss;
        g_part[(g * NSUB + sub) * 2 * C + C + t] = qq;
    }
}

template <int C>
__global__ void gn_final_kernel(const float* __restrict__ w, const float* __restrict__ sc) {
    int g = blockIdx.x, c = threadIdx.x;
    int beg = g_go[g], end = g_go[g + 1];
    float cnt = fmaxf((float)(end - beg), 1.f);
    float s = 0.f, q = 0.f;
    for (int sub = 0; sub < NSUB; sub++) {
        s += g_part[(g * NSUB + sub) * 2 * C + c];
        q += g_part[(g * NSUB + sub) * 2 * C + C + c];
    }
    float mu = s / cnt;
    float mus = mu * sc[c];
    float var = q / cnt - 2.f * mus * mu + mus * mus;
    g_mus[g * C + c] = mus;
    g_wr[g * C + c] = w[c] * rsqrtf(var + 1e-5f);
}

template <int C>
__global__ void gn_norm_kernel(const float* __restrict__ x, float* __restrict__ y,
                               const float* __restrict__ b, const int* __restrict__ batch) {
    int i4 = blockIdx.x * blockDim.x + threadIdx.x;
    if (i4 >= NN * C / 4) return;
    int idx = i4 * 4;
    int node = idx / C, c = idx % C;
    int g = batch[node];
    float4 xv = *reinterpret_cast<const float4*>(x + idx);
    float4 mv = *reinterpret_cast<const float4*>(g_mus + g * C + c);
    float4 wv = *reinterpret_cast<const float4*>(g_wr + g * C + c);
    float4 bv = *reinterpret_cast<const float4*>(b + c);
    float4 o;
    o.x = fmaxf(fmaf(xv.x - mv.x, wv.x, bv.x), 0.f);
    o.y = fmaxf(fmaf(xv.y - mv.y, wv.y, bv.y), 0.f);
    o.z = fmaxf(fmaf(xv.z - mv.z, wv.z, bv.z), 0.f);
    o.w = fmaxf(fmaf(xv.w - mv.w, wv.w, bv.w), 0.f);
    *reinterpret_cast<float4*>(y + idx) = o;
}

// ---------------- pool + linear ----------------
__global__ void pool_linear_kernel(const float* __restrict__ h, const float* __restrict__ lw,
                                   const float* __restrict__ lb, float* __restrict__ out) {
    __shared__ float red[256];
    __shared__ float feat[8];
    int g = blockIdx.x;
    int beg = g_go[g], end = g_go[g + 1];
    float fcnt = fmaxf((float)(end - beg), 1.f);
    int t = threadIdx.x;
    int c = t & 7, r = t >> 3;
    float sum = 0.f;
    for (int i = beg + r; i < end; i += 32) sum += h[(size_t)i * 8 + c];
    red[t] = sum; __syncthreads();
    if (t < 8) { float v = 0.f; for (int k = t; k < 256; k += 8) v += red[k]; feat[t] = v / fcnt; }
    __syncthreads();
    if (t < 8) out[NG * 4 + g * 8 + t] = feat[t];   // features after logits block
    if (t < 4) {
        float v = lb[t];
#pragma unroll
        for (int c2 = 0; c2 < 8; c2++) v = fmaf(feat[c2], lw[c2 * 4 + t], v);
        out[g * 4 + t] = v;                          // logits
    }
}

// ---------------- host orchestration ----------------
static void launch_gemm_dual(const float* A, int bOff0, int bOff1,
                             float* C0, float* C1, int N, int K, int M) {
    dim3 grid((M + 63) / 64, (N + 127) / 128, 2);
    gemm_bf16_dual<<<grid, 256>>>(A, bOff0, bOff1, C0, C1, N, K, M);
}

template <int C>
static void launch_graphnorm(const float* x, float* y, const float* w, const float* b,
                             const float* s, const int* batch) {
    gn_part_kernel<C><<<dim3(NG, NSUB), 256>>>(x);
    gn_final_kernel<C><<<NG, C>>>(w, s);
    gn_norm_kernel<C><<<(NN * C / 4 + 255) / 256, 256>>>(x, y, b, batch);
}

extern "C" void kernel_launch(void* const* d_in, const int* in_sizes, int n_in,
                              void* d_out, int out_size) {
    const float* x     = (const float*)d_in[0];
    const int*   ei    = (const int*)d_in[1];
    const int*   batch = (const int*)d_in[2];
    const float* w_l1 = (const float*)d_in[3];
    const float* w_r1 = (const float*)d_in[4];
    const float* att1 = (const float*)d_in[5];
    const float* b1   = (const float*)d_in[6];
    const float* gn1w = (const float*)d_in[7];
    const float* gn1b = (const float*)d_in[8];
    const float* gn1s = (const float*)d_in[9];
    const float* w_l2 = (const float*)d_in[10];
    const float* w_r2 = (const float*)d_in[11];
    const float* att2 = (const float*)d_in[12];
    const float* b2   = (const float*)d_in[13];
    const float* gn2w = (const float*)d_in[14];
    const float* gn2b = (const float*)d_in[15];
    const float* gn2s = (const float*)d_in[16];
    const float* w_l3 = (const float*)d_in[17];
    const float* w_r3 = (const float*)d_in[18];
    const float* att3 = (const float*)d_in[19];
    const float* b3   = (const float*)d_in[20];
    const float* gn3w = (const float*)d_in[21];
    const float* gn3b = (const float*)d_in[22];
    const float* gn3s = (const float*)d_in[23];
    const float* linw = (const float*)d_in[24];
    const float* linb = (const float*)d_in[25];
    float* out = (float*)d_out;

    float *xl, *xr, *h1, *h2, *h3;
    cudaGetSymbolAddress((void**)&xl, g_xl);
    cudaGetSymbolAddress((void**)&xr, g_xr);
    cudaGetSymbolAddress((void**)&h1, g_h1);
    cudaGetSymbolAddress((void**)&h2, g_h2);
    cudaGetSymbolAddress((void**)&h3, g_h3);

    // launch order keeps the layer-1 GEMM at slot 3 (ncu capture target)
    zero_deg_kernel<<<(NN + 255) / 256, 256>>>();                         // 0
    count_deg_kernel<<<(ETOT + 255) / 256, 256>>>(ei);                    // 1
    split_b_kernel<<<(BTOT + 255) / 256, 256>>>(w_l1, w_r1, w_l2, w_r2,
                                                w_l3, w_r3);              // 2
    launch_gemm_dual(x, OFF_L1_0, OFF_L1_1, xl, xr, NN, 128, 128);        // 3 (capture)
    scan_kernel<<<1, 1024>>>(batch);                                      // 4
    scatter_kernel<<<(ETOT + 255) / 256, 256>>>(ei);                      // 5

    const int GAT_BLOCKS = (NN * 32 + 255) / 256;

    // layer 1: 128 -> 4x32 concat = 128
    gat_kernel<32, false><<<GAT_BLOCKS, 256>>>(xl, xr, att1, b1, h1);
    launch_graphnorm<128>(h1, h1, gn1w, gn1b, gn1s, batch);

    // layer 2: 128 -> 4x16 concat = 64
    launch_gemm_dual(h1, OFF_L2_0, OFF_L2_1, xl, xr, NN, 128, 64);
    gat_kernel<16, false><<<GAT_BLOCKS, 256>>>(xl, xr, att2, b2, h2);
    launch_graphnorm<64>(h2, h2, gn2w, gn2b, gn2s, batch);

    // layer 3: 64 -> 4x8 mean = 8
    launch_gemm_dual(h2, OFF_L3_0, OFF_L3_1, xl, xr, NN, 64, 32);
    gat_kernel<8, true><<<GAT_BLOCKS, 256>>>(xl, xr, att3, b3, h3);
    launch_graphnorm<8>(h3, h3, gn3w, gn3b, gn3s, batch);

    // pool + linear: out[0:256] logits, out[256:768] features
    pool_linear_kernel<<<NG, 256>>>(h3, linw, linb, out);
}

// round 10
// speedup vs baseline: 1.3265x; 1.0306x over previous
#include <cuda_runtime.h>
#include <cuda_bf16.h>
#include <math_constants.h>

// Problem constants (fixed by the dataset)
#define NN 50000
#define NE 800000
#define ETOT (NE + NN)       // edges + self loops = 850000
#define NG 64
#define HEADS 4
#define NSUB 8               // GraphNorm sub-partitions per graph

// ---------------- scratch (no cudaMalloc allowed) ----------------
__device__ float g_xl[NN * 128];
__device__ float g_xr[NN * 128];
__device__ float g_h1[NN * 128];
__device__ float g_h2[NN * 64];
__device__ float g_h3[NN * 8];
__device__ int   g_deg[NN];      // zero-init at load; re-zeroed by scatter each call
__device__ int   g_off[NN + 1];
__device__ int   g_cursor[NN];
__device__ int   g_srcs[ETOT];
__device__ int   g_go[NG + 1];
__device__ float g_part[NG * NSUB * 2 * 128];
__device__ float g_mus[NG * 128];
__device__ float g_wr[NG * 128];

// packed bf16x2 hi/lo weight buffers (k-pairs x M), all 6 matrices
#define OFF_L1_0 0
#define OFF_L1_1 8192
#define OFF_L2_0 16384
#define OFF_L2_1 20480
#define OFF_L3_0 24576
#define OFF_L3_1 25600
#define BTOT 26624
__device__ unsigned g_bh[BTOT];
__device__ unsigned g_bl[BTOT];

// ---------------- cp.async helpers ----------------
__device__ __forceinline__ void cp_async16(void* smem_ptr, const void* gmem_ptr, bool pred) {
    unsigned saddr = (unsigned)__cvta_generic_to_shared(smem_ptr);
    int sz = pred ? 16 : 0;
    asm volatile("cp.async.ca.shared.global [%0], [%1], 16, %2;\n"
                 :: "r"(saddr), "l"(gmem_ptr), "r"(sz));
}
__device__ __forceinline__ void cp_commit() { asm volatile("cp.async.commit_group;\n"); }
template <int N>
__device__ __forceinline__ void cp_wait() { asm volatile("cp.async.wait_group %0;\n" :: "n"(N)); }

// ---------------- bf16 split helpers ----------------
__device__ __forceinline__ void split_bf16x2(float v0, float v1, unsigned& hi, unsigned& lo) {
    asm("cvt.rn.bf16x2.f32 %0, %1, %2;" : "=r"(hi) : "f"(v1), "f"(v0));
    float f0 = __uint_as_float(hi << 16);
    float f1 = __uint_as_float(hi & 0xffff0000u);
    asm("cvt.rn.bf16x2.f32 %0, %1, %2;" : "=r"(lo) : "f"(v1 - f1), "f"(v0 - f0));
}

__device__ __forceinline__ void mma_bf16(float c[4], unsigned a0, unsigned a1,
                                         unsigned a2, unsigned a3,
                                         unsigned b0, unsigned b1) {
    asm volatile(
        "mma.sync.aligned.m16n8k16.row.col.f32.bf16.bf16.f32 "
        "{%0,%1,%2,%3}, {%4,%5,%6,%7}, {%8,%9}, {%0,%1,%2,%3};\n"
        : "+f"(c[0]), "+f"(c[1]), "+f"(c[2]), "+f"(c[3])
        : "r"(a0), "r"(a1), "r"(a2), "r"(a3), "r"(b0), "r"(b1));
}

// ---------------- weight pre-split (all 6 matrices, one launch) ----------------
__global__ void split_b_kernel(const float* __restrict__ b10, const float* __restrict__ b11,
                               const float* __restrict__ b20, const float* __restrict__ b21,
                               const float* __restrict__ b30, const float* __restrict__ b31) {
    int i = blockIdx.x * blockDim.x + threadIdx.x;
    if (i >= BTOT) return;
    const float* B; int M, local;
    if (i < OFF_L1_1)      { B = b10; M = 128; local = i; }
    else if (i < OFF_L2_0) { B = b11; M = 128; local = i - OFF_L1_1; }
    else if (i < OFF_L2_1) { B = b20; M = 64;  local = i - OFF_L2_0; }
    else if (i < OFF_L3_0) { B = b21; M = 64;  local = i - OFF_L2_1; }
    else if (i < OFF_L3_1) { B = b30; M = 32;  local = i - OFF_L3_0; }
    else                   { B = b31; M = 32;  local = i - OFF_L3_1; }
    int kp = local / M, n = local % M;
    float v0 = B[(size_t)(2 * kp) * M + n];
    float v1 = B[(size_t)(2 * kp + 1) * M + n];
    unsigned hi, lo;
    split_bf16x2(v0, v1, hi, lo);
    g_bh[i] = hi;
    g_bl[i] = lo;
}

// ---------------- CSR build ----------------
__global__ void count_deg_kernel(const int* __restrict__ ei) {
    int e = blockIdx.x * blockDim.x + threadIdx.x;
    if (e >= ETOT) return;
    int dst = (e < NE) ? ei[NE + e] : (e - NE);
    atomicAdd(&g_deg[dst], 1);
}

// single-block exclusive scan (warp-shuffle based) + graph offsets
__global__ void scan_kernel(const int* __restrict__ batch) {
    __shared__ int wsum[32];
    __shared__ int carry_s;
    int t = threadIdx.x, lane = t & 31, wid = t >> 5;
    if (t == 0) carry_s = 0;
    __syncthreads();
    for (int base = 0; base < NN; base += 1024) {
        int i = base + t;
        int v = (i < NN) ? g_deg[i] : 0;
        int s = v;
#pragma unroll
        for (int o = 1; o < 32; o <<= 1) {
            int n = __shfl_up_sync(0xffffffffu, s, o);
            if (lane >= o) s += n;
        }
        if (lane == 31) wsum[wid] = s;
        __syncthreads();
        if (wid == 0) {
            int ws = wsum[lane];
#pragma unroll
            for (int o = 1; o < 32; o <<= 1) {
                int n = __shfl_up_sync(0xffffffffu, ws, o);
                if (lane >= o) ws += n;
            }
            wsum[lane] = ws;
        }
        __syncthreads();
        int carry = carry_s;
        int excl = carry + (wid ? wsum[wid - 1] : 0) + s - v;
        if (i < NN) { g_off[i] = excl; g_cursor[i] = excl; }
        int total = wsum[31];
        __syncthreads();
        if (t == 0) carry_s = carry + total;
        __syncthreads();
    }
    if (t == 0) g_off[NN] = carry_s;
    if (t <= NG) {
        if (t == NG) g_go[NG] = NN;
        else {
            int lo = 0, hi = NN;
            while (lo < hi) {
                int mid = (lo + hi) >> 1;
                if (batch[mid] < t) lo = mid + 1; else hi = mid;
            }
            g_go[t] = lo;
        }
    }
}

__global__ void scatter_kernel(const int* __restrict__ ei) {
    int e = blockIdx.x * blockDim.x + threadIdx.x;
    if (e >= ETOT) return;
    if (e < NN) g_deg[e] = 0;   // reset for next call (deg dead after scan)
    int src, dst;
    if (e < NE) { src = ei[e]; dst = ei[NE + e]; }
    else        { src = dst = e - NE; }
    int pos = atomicAdd(&g_cursor[dst], 1);
    g_srcs[pos] = src;
}

// ---------------- 3xBF16 tensor-core GEMM (A split at STS; optional fused GN) --
// C[N,M] = A'[N,K] @ B[K,M] where A' = NORM ? relu((A - mus)*wr + gb) : A.
// B pre-split on device (g_bh/g_bl). Block tile 128x64, 8 warps, m16n8k16.
template <bool NORM>
__global__ __launch_bounds__(256) void gemm_bf16_dual(
    const float* __restrict__ A,
    int bOff0, int bOff1,
    float* __restrict__ Cp0, float* __restrict__ Cp1,
    int N, int K, int M,
    const float* __restrict__ gb, const int* __restrict__ batch) {
    int bOff = blockIdx.z ? bOff1 : bOff0;
    float* C = blockIdx.z ? Cp1 : Cp0;
    const unsigned* Bh = g_bh + bOff;
    const unsigned* Bl = g_bl + bOff;

    __shared__ unsigned Ash[2][8][136];  // [kpair][row], stride 136 (≡8 mod 32)
    __shared__ unsigned Asl[2][8][136];
    __shared__ unsigned Bsh[2][8][72];   // [kpair][col]
    __shared__ unsigned Bsl[2][8][72];

    int t = threadIdx.x;
    int w = t >> 5, lane = t & 31;
    int wr = w >> 1, wc = w & 1;         // 4x2 warp grid
    int grp = lane >> 2, tg = lane & 3;
    int row0 = blockIdx.y * 128;
    int col0 = blockIdx.x * 64;

    float c[2][4][4];
#pragma unroll
    for (int i = 0; i < 2; i++)
#pragma unroll
        for (int j = 0; j < 4; j++)
#pragma unroll
            for (int k = 0; k < 4; k++) c[i][j][k] = 0.f;

    float4 areg[2];

    auto lda_regs = [&](int kt) {
        int k0 = kt << 4;
#pragma unroll
        for (int u = 0; u < 2; u++) {
            int i = t + u * 256;
            int r = i >> 2, c4 = (i & 3) * 4;
            int gr = row0 + r;
            if (gr < N) {
                float4 a = *reinterpret_cast<const float4*>(A + (size_t)gr * K + k0 + c4);
                if (NORM) {
                    int g = batch[gr];
                    float4 mv = *reinterpret_cast<const float4*>(g_mus + (size_t)g * K + k0 + c4);
                    float4 wv = *reinterpret_cast<const float4*>(g_wr  + (size_t)g * K + k0 + c4);
                    float4 bv = *reinterpret_cast<const float4*>(gb + k0 + c4);
                    a.x = fmaxf(fmaf(a.x - mv.x, wv.x, bv.x), 0.f);
                    a.y = fmaxf(fmaf(a.y - mv.y, wv.y, bv.y), 0.f);
                    a.z = fmaxf(fmaf(a.z - mv.z, wv.z, bv.z), 0.f);
                    a.w = fmaxf(fmaf(a.w - mv.w, wv.w, bv.w), 0.f);
                }
                areg[u] = a;
            } else {
                areg[u] = make_float4(0.f, 0.f, 0.f, 0.f);
            }
        }
    };
    auto sts_a = [&](int stage) {
#pragma unroll
        for (int u = 0; u < 2; u++) {
            int i = t + u * 256;
            int r = i >> 2, kp = (i & 3) * 2;
            unsigned h0, l0, h1, l1;
            split_bf16x2(areg[u].x, areg[u].y, h0, l0);
            split_bf16x2(areg[u].z, areg[u].w, h1, l1);
            Ash[stage][kp][r] = h0; Ash[stage][kp + 1][r] = h1;
            Asl[stage][kp][r] = l0; Asl[stage][kp + 1][r] = l1;
        }
    };
    auto ldb_async = [&](int stage, int kt) {
        int buf = t >> 7;                // 0 = hi, 1 = lo
        int rem = t & 127;
        int r = rem >> 4, c4 = (rem & 15) * 4;
        bool p = (col0 + c4) < M;
        const unsigned* Bsel = buf ? Bl : Bh;
        const unsigned* src = p ? (Bsel + (size_t)(kt * 8 + r) * M + col0 + c4) : Bh;
        unsigned* dst = buf ? &Bsl[stage][r][c4] : &Bsh[stage][r][c4];
        cp_async16(dst, src, p);
    };

    int KT = K >> 4;
    lda_regs(0);
    ldb_async(0, 0);
    cp_commit();
    sts_a(0);

    for (int kt = 0; kt < KT; kt++) {
        int cur = kt & 1;
        if (kt + 1 < KT) {
            lda_regs(kt + 1);            // overlap LDG with compute below
            ldb_async(cur ^ 1, kt + 1);
            cp_commit();
            cp_wait<1>();
        } else {
            cp_wait<0>();
        }
        __syncthreads();                 // stage `cur` fully ready

        unsigned ah[2][4], al[2][4];
#pragma unroll
        for (int mt = 0; mt < 2; mt++) {
            int r0 = wr * 32 + mt * 16;
            ah[mt][0] = Ash[cur][tg][r0 + grp];
            ah[mt][1] = Ash[cur][tg][r0 + grp + 8];
            ah[mt][2] = Ash[cur][tg + 4][r0 + grp];
            ah[mt][3] = Ash[cur][tg + 4][r0 + grp + 8];
            al[mt][0] = Asl[cur][tg][r0 + grp];
            al[mt][1] = Asl[cur][tg][r0 + grp + 8];
            al[mt][2] = Asl[cur][tg + 4][r0 + grp];
            al[mt][3] = Asl[cur][tg + 4][r0 + grp + 8];
        }
#pragma unroll
        for (int nt = 0; nt < 4; nt++) {
            int ci = wc * 32 + nt * 8 + grp;
            unsigned bh0 = Bsh[cur][tg][ci];
            unsigned bh1 = Bsh[cur][tg + 4][ci];
            unsigned bl0 = Bsl[cur][tg][ci];
            unsigned bl1 = Bsl[cur][tg + 4][ci];
#pragma unroll
            for (int mt = 0; mt < 2; mt++) {
                mma_bf16(c[mt][nt], ah[mt][0], ah[mt][1], ah[mt][2], ah[mt][3], bh0, bh1);
                mma_bf16(c[mt][nt], al[mt][0], al[mt][1], al[mt][2], al[mt][3], bh0, bh1);
                mma_bf16(c[mt][nt], ah[mt][0], ah[mt][1], ah[mt][2], ah[mt][3], bl0, bl1);
            }
        }
        if (kt + 1 < KT) sts_a(cur ^ 1); // safe: stage cur^1 not read this iter
        __syncthreads();
    }

#pragma unroll
    for (int mt = 0; mt < 2; mt++) {
#pragma unroll
        for (int nt = 0; nt < 4; nt++) {
            int gc = col0 + wc * 32 + nt * 8 + 2 * tg;
            if (gc >= M) continue;
            int gr0 = row0 + wr * 32 + mt * 16 + grp;
            if (gr0 < N) {
                float2 v = make_float2(c[mt][nt][0], c[mt][nt][1]);
                *reinterpret_cast<float2*>(C + (size_t)gr0 * M + gc) = v;
            }
            int gr1 = gr0 + 8;
            if (gr1 < N) {
                float2 v = make_float2(c[mt][nt][2], c[mt][nt][3]);
                *reinterpret_cast<float2*>(C + (size_t)gr1 * M + gc) = v;
            }
        }
    }
}

// ---------------- GATv2: warp per dst node, online softmax, 4-edge unroll ----
template <int V>
__device__ __forceinline__ void load_row(float* d, const float* p) {
    if (V == 4) {
        float4 t = *reinterpret_cast<const float4*>(p);
        d[0] = t.x; d[1] = t.y; d[V > 2 ? 2 : 0] = t.z; d[V > 3 ? 3 : 0] = t.w;
    } else if (V == 2) {
        float2 t = *reinterpret_cast<const float2*>(p);
        d[0] = t.x; d[V > 1 ? 1 : 0] = t.y;
    } else {
        d[0] = p[0];
    }
}

template <int V>
__device__ __forceinline__ float edge_score(const float* cur, const float* xrv,
                                            const float* attv) {
    float part = 0.f;
#pragma unroll
    for (int v = 0; v < V; v++) {
        float m = cur[v] + xrv[v];
        m = (m > 0.f) ? m : 0.2f * m;
        part = fmaf(attv[v], m, part);
    }
    part += __shfl_xor_sync(0xffffffffu, part, 1);
    part += __shfl_xor_sync(0xffffffffu, part, 2);
    part += __shfl_xor_sync(0xffffffffu, part, 4);
    return part;
}

template <int C, bool MEAN>
__global__ void gat_kernel(const float* __restrict__ xl, const float* __restrict__ xr,
                           const float* __restrict__ att, const float* __restrict__ bias,
                           float* __restrict__ out) {
    constexpr int H = HEADS;
    constexpr int HC = H * C;
    constexpr int V = HC / 32;
    int warp = (blockIdx.x * blockDim.x + threadIdx.x) >> 5;
    int lane = threadIdx.x & 31;
    if (warp >= NN) return;
    int node = warp;

    float attv[V], xrv[V], acc[V];
#pragma unroll
    for (int v = 0; v < V; v++) {
        attv[v] = att[lane * V + v];
        xrv[v]  = xr[node * HC + lane * V + v];
        acc[v]  = 0.f;
    }
    float mrun = -CUDART_INF_F, lrun = 0.f;
    int beg = g_off[node], end = g_off[node + 1];
    const size_t lo = (size_t)lane * V;

    // four independent prefetch slots (explicit regs, compile-time indices)
    float p0[V], p1[V], p2[V], p3[V];
    load_row<V>(p0, xl + (size_t)g_srcs[beg] * HC + lo);
    if (beg + 1 < end) load_row<V>(p1, xl + (size_t)g_srcs[beg + 1] * HC + lo);
    if (beg + 2 < end) load_row<V>(p2, xl + (size_t)g_srcs[beg + 2] * HC + lo);
    if (beg + 3 < end) load_row<V>(p3, xl + (size_t)g_srcs[beg + 3] * HC + lo);

    auto single = [&](const float* pk) {
        float e = edge_score<V>(pk, xrv, attv);
        float nm = fmaxf(mrun, e);
        float sc = __expf(mrun - nm);
        float w  = __expf(e - nm);
#pragma unroll
        for (int v = 0; v < V; v++) acc[v] = fmaf(acc[v], sc, w * pk[v]);
        lrun = fmaf(lrun, sc, w);
        mrun = nm;
    };

    int j = beg;
    for (; j + 4 <= end; j += 4) {
        float c0[V], c1[V], c2[V], c3[V];
#pragma unroll
        for (int v = 0; v < V; v++) {
            c0[v] = p0[v]; c1[v] = p1[v]; c2[v] = p2[v]; c3[v] = p3[v];
        }
        if (j + 4 < end) load_row<V>(p0, xl + (size_t)g_srcs[j + 4] * HC + lo);
        if (j + 5 < end) load_row<V>(p1, xl + (size_t)g_srcs[j + 5] * HC + lo);
        if (j + 6 < end) load_row<V>(p2, xl + (size_t)g_srcs[j + 6] * HC + lo);
        if (j + 7 < end) load_row<V>(p3, xl + (size_t)g_srcs[j + 7] * HC + lo);

        float e0 = edge_score<V>(c0, xrv, attv);
        float e1 = edge_score<V>(c1, xrv, attv);
        float e2 = edge_score<V>(c2, xrv, attv);
        float e3 = edge_score<V>(c3, xrv, attv);
        float nm = fmaxf(fmaxf(fmaxf(e0, e1), fmaxf(e2, e3)), mrun);
        float sc = __expf(mrun - nm);
        float w0 = __expf(e0 - nm);
        float w1 = __expf(e1 - nm);
        float w2 = __expf(e2 - nm);
        float w3 = __expf(e3 - nm);
#pragma unroll
        for (int v = 0; v < V; v++)
            acc[v] = fmaf(acc[v], sc,
                     fmaf(w0, c0[v], fmaf(w1, c1[v], fmaf(w2, c2[v], w3 * c3[v]))));
        lrun = fmaf(lrun, sc, (w0 + w1) + (w2 + w3));
        mrun = nm;
    }
    // tail 0..3 edges live in p0..p2
    if (j < end)     single(p0);
    if (j + 1 < end) single(p1);
    if (j + 2 < end) single(p2);

    float inv = 1.f / lrun;
    if (!MEAN) {
#pragma unroll
        for (int v = 0; v < V; v++)
            out[(size_t)node * HC + lane * V + v] = acc[v] * inv + bias[lane * V + v];
    } else {
        float r = acc[0] * inv;
        r += __shfl_xor_sync(0xffffffffu, r, 8);
        r += __shfl_xor_sync(0xffffffffu, r, 16);
        r *= 0.25f;
        if (lane < 8) out[(size_t)node * 8 + lane] = r + bias[lane];
    }
}

// ---------------- GraphNorm stats (2-kernel; normalize fused into next GEMM) --
template <int C>
__global__ void gn_part_kernel(const float* __restrict__ x) {
    constexpr int R = 256 / C;
    __shared__ float red[256], red2[256];
    int g = blockIdx.x, sub = blockIdx.y;
    int beg = g_go[g], end = g_go[g + 1];
    int t = threadIdx.x, c = t % C, r = t / C;
    float s = 0.f, q = 0.f;
    for (int i = beg + sub * R + r; i < end; i += NSUB * R) {
        float v = x[(size_t)i * C + c];
        s += v; q = fmaf(v, v, q);
    }
    red[t] = s; red2[t] = q;
    __syncthreads();
    if (t < C) {
        float ss = 0.f, qq = 0.f;
        for (int k = t; k < 256; k += C) { ss += red[k]; qq += red2[k]; }
        g_part[(g * NSUB + sub) * 2 * C + t] = ss;
        g_part[(g * NSUB + sub) * 2 * C + C + t] = qq;
    }
}

template <int C>
__global__ void gn_final_kernel(const float* __restrict__ w, const float* __restrict__ sc) {
    int g = blockIdx.x, c = threadIdx.x;
    int beg = g_go[g], end = g_go[g + 1];
    float cnt = fmaxf((float)(end - beg), 1.f);
    float s = 0.f, q = 0.f;
    for (int sub = 0; sub < NSUB; sub++) {
        s += g_part[(g * NSUB + sub) * 2 * C + c];
        q += g_part[(g * NSUB + sub) * 2 * C + C + c];
    }
    float mu = s / cnt;
    float mus = mu * sc[c];
    float var = q / cnt - 2.f * mus * mu + mus * mus;
    g_mus[g * C + c] = mus;
    g_wr[g * C + c] = w[c] * rsqrtf(var + 1e-5f);
}

template <int C>
__global__ void gn_norm_kernel(const float* __restrict__ x, float* __restrict__ y,
                               const float* __restrict__ b, const int* __restrict__ batch) {
    int i4 = blockIdx.x * blockDim.x + threadIdx.x;
    if (i4 >= NN * C / 4) return;
    int idx = i4 * 4;
    int node = idx / C, c = idx % C;
    int g = batch[node];
    float4 xv = *reinterpret_cast<const float4*>(x + idx);
    float4 mv = *reinterpret_cast<const float4*>(g_mus + g * C + c);
    float4 wv = *reinterpret_cast<const float4*>(g_wr + g * C + c);
    float4 bv = *reinterpret_cast<const float4*>(b + c);
    float4 o;
    o.x = fmaxf(fmaf(xv.x - mv.x, wv.x, bv.x), 0.f);
    o.y = fmaxf(fmaf(xv.y - mv.y, wv.y, bv.y), 0.f);
    o.z = fmaxf(fmaf(xv.z - mv.z, wv.z, bv.z), 0.f);
    o.w = fmaxf(fmaf(xv.w - mv.w, wv.w, bv.w), 0.f);
    *reinterpret_cast<float4*>(y + idx) = o;
}

// ---------------- pool + linear ----------------
__global__ void pool_linear_kernel(const float* __restrict__ h, const float* __restrict__ lw,
                                   const float* __restrict__ lb, float* __restrict__ out) {
    __shared__ float red[256];
    __shared__ float feat[8];
    int g = blockIdx.x;
    int beg = g_go[g], end = g_go[g + 1];
    float fcnt = fmaxf((float)(end - beg), 1.f);
    int t = threadIdx.x;
    int c = t & 7, r = t >> 3;
    float sum = 0.f;
    for (int i = beg + r; i < end; i += 32) sum += h[(size_t)i * 8 + c];
    red[t] = sum; __syncthreads();
    if (t < 8) { float v = 0.f; for (int k = t; k < 256; k += 8) v += red[k]; feat[t] = v / fcnt; }
    __syncthreads();
    if (t < 8) out[NG * 4 + g * 8 + t] = feat[t];   // features after logits block
    if (t < 4) {
        float v = lb[t];
#pragma unroll
        for (int c2 = 0; c2 < 8; c2++) v = fmaf(feat[c2], lw[c2 * 4 + t], v);
        out[g * 4 + t] = v;                          // logits
    }
}

// ---------------- host orchestration ----------------
template <bool NORM>
static void launch_gemm_dual(const float* A, int bOff0, int bOff1,
                             float* C0, float* C1, int N, int K, int M,
                             const float* gb, const int* batch) {
    dim3 grid((M + 63) / 64, (N + 127) / 128, 2);
    gemm_bf16_dual<NORM><<<grid, 256>>>(A, bOff0, bOff1, C0, C1, N, K, M, gb, batch);
}

extern "C" void kernel_launch(void* const* d_in, const int* in_sizes, int n_in,
                              void* d_out, int out_size) {
    const float* x     = (const float*)d_in[0];
    const int*   ei    = (const int*)d_in[1];
    const int*   batch = (const int*)d_in[2];
    const float* w_l1 = (const float*)d_in[3];
    const float* w_r1 = (const float*)d_in[4];
    const float* att1 = (const float*)d_in[5];
    const float* b1   = (const float*)d_in[6];
    const float* gn1w = (const float*)d_in[7];
    const float* gn1b = (const float*)d_in[8];
    const float* gn1s = (const float*)d_in[9];
    const float* w_l2 = (const float*)d_in[10];
    const float* w_r2 = (const float*)d_in[11];
    const float* att2 = (const float*)d_in[12];
    const float* b2   = (const float*)d_in[13];
    const float* gn2w = (const float*)d_in[14];
    const float* gn2b = (const float*)d_in[15];
    const float* gn2s = (const float*)d_in[16];
    const float* w_l3 = (const float*)d_in[17];
    const float* w_r3 = (const float*)d_in[18];
    const float* att3 = (const float*)d_in[19];
    const float* b3   = (const float*)d_in[20];
    const float* gn3w = (const float*)d_in[21];
    const float* gn3b = (const float*)d_in[22];
    const float* gn3s = (const float*)d_in[23];
    const float* linw = (const float*)d_in[24];
    const float* linb = (const float*)d_in[25];
    float* out = (float*)d_out;

    float *xl, *xr, *h1, *h2, *h3;
    cudaGetSymbolAddress((void**)&xl, g_xl);
    cudaGetSymbolAddress((void**)&xr, g_xr);
    cudaGetSymbolAddress((void**)&h1, g_h1);
    cudaGetSymbolAddress((void**)&h2, g_h2);
    cudaGetSymbolAddress((void**)&h3, g_h3);

    // launch order keeps the layer-1 GEMM at slot 3 (ncu capture target)
    count_deg_kernel<<<(ETOT + 255) / 256, 256>>>(ei);                    // 0
    split_b_kernel<<<(BTOT + 255) / 256, 256>>>(w_l1, w_r1, w_l2, w_r2,
                                                w_l3, w_r3);              // 1
    scan_kernel<<<1, 1024>>>(batch);                                      // 2
    launch_gemm_dual<false>(x, OFF_L1_0, OFF_L1_1, xl, xr,
                            NN, 128, 128, nullptr, nullptr);              // 3 (capture)
    scatter_kernel<<<(ETOT + 255) / 256, 256>>>(ei);                      // 4

    const int GAT_BLOCKS = (NN * 32 + 255) / 256;

    // layer 1: 128 -> 4x32 concat = 128
    gat_kernel<32, false><<<GAT_BLOCKS, 256>>>(xl, xr, att1, b1, h1);
    gn_part_kernel<128><<<dim3(NG, NSUB), 256>>>(h1);
    gn_final_kernel<128><<<NG, 128>>>(gn1w, gn1s);

    // layer 2: 128 -> 4x16 concat = 64 (GN of h1 fused into A-load)
    launch_gemm_dual<true>(h1, OFF_L2_0, OFF_L2_1, xl, xr,
                           NN, 128, 64, gn1b, batch);
    gat_kernel<16, false><<<GAT_BLOCKS, 256>>>(xl, xr, att2, b2, h2);
    gn_part_kernel<64><<<dim3(NG, NSUB), 256>>>(h2);
    gn_final_kernel<64><<<NG, 64>>>(gn2w, gn2s);

    // layer 3: 64 -> 4x8 mean = 8 (GN of h2 fused into A-load)
    launch_gemm_dual<true>(h2, OFF_L3_0, OFF_L3_1, xl, xr,
                           NN, 64, 32, gn2b, batch);
    gat_kernel<8, true><<<GAT_BLOCKS, 256>>>(xl, xr, att3, b3, h3);
    gn_part_kernel<8><<<dim3(NG, NSUB), 256>>>(h3);
    gn_final_kernel<8><<<NG, 8>>>(gn3w, gn3s);
    gn_norm_kernel<8><<<(NN * 8 / 4 + 255) / 256, 256>>>(h3, h3, gn3b, batch);

    // pool + linear: out[0:256] logits, out[256:768] features
    pool_linear_kernel<<<NG, 256>>>(h3, linw, linb, out);
}